// round 2
// baseline (speedup 1.0000x reference)
#include <cuda_runtime.h>
#include <math.h>

// ---------------- problem constants ----------------
#define MAXN 10000
#define MAXE 160000
// HC = 256, C = 64, H = 4

// ---------------- scratch (device globals; no allocation) ----------------
__device__ float g_Xni[MAXN * 256];
__device__ float g_Xnj[MAXN * 256];
__device__ float g_Xnt[MAXN * 64];
__device__ float g_Et [MAXE * 64];
__device__ float g_F  [MAXE * 768];
__device__ float g_H0 [MAXE * 256];
__device__ float g_H1 [MAXE * 256];
__device__ float g_H2 [MAXE * 256];
__device__ float g_EM0[MAXE * 64];
__device__ float g_EM1[MAXE * 64];
__device__ float g_scores[MAXE * 4];
__device__ float g_ex  [MAXE * 4];
__device__ float g_smax[MAXN * 4];
__device__ float g_den [MAXN * 4];
__device__ float g_agg [MAXN * 256];
__device__ float g_NM0 [MAXN * 64];
__device__ float g_NM1 [MAXN * 64];
__device__ float g_nodeout[MAXN * 64];
__device__ float g_deg [MAXN];
__device__ float g_dinv[MAXN];
__device__ float g_xg  [MAXN * 64];

// ---------------- generic tiled SGEMM ----------------
// C[M,N] = epilogue(A[M,K](lda) @ W[K,N]) ; W row-major with leading dim N.
// epilogue: (+bias) -> relu -> (+res)
template<int BM, int BN, int BK, int TM, int TN, bool RELU, bool BIAS, bool RES>
__global__ void __launch_bounds__((BM / TM) * (BN / TN))
sgemm(const float* __restrict__ A, int lda,
      const float* __restrict__ W,
      const float* __restrict__ bias,
      const float* __restrict__ res, int ldres,
      float* __restrict__ C, int ldc,
      int M, int N, int K)
{
    constexpr int NT = (BM / TM) * (BN / TN);
    __shared__ float As[BK][BM + 4];
    __shared__ float Ws[BK][BN];

    const int tid = threadIdx.x;
    const int tx = tid % (BN / TN);
    const int ty = tid / (BN / TN);
    const int m0 = blockIdx.x * BM;
    const int n0 = blockIdx.y * BN;

    float acc[TM][TN];
#pragma unroll
    for (int i = 0; i < TM; i++)
#pragma unroll
        for (int j = 0; j < TN; j++) acc[i][j] = 0.0f;

    for (int k0 = 0; k0 < K; k0 += BK) {
        // load A tile (transposed into shared)
#pragma unroll
        for (int i = tid; i < BM * BK / 4; i += NT) {
            int m  = i / (BK / 4);
            int k4 = i % (BK / 4);
            float4 v = make_float4(0.f, 0.f, 0.f, 0.f);
            int row = m0 + m;
            if (row < M)
                v = *reinterpret_cast<const float4*>(A + (size_t)row * lda + k0 + k4 * 4);
            As[k4 * 4 + 0][m] = v.x;
            As[k4 * 4 + 1][m] = v.y;
            As[k4 * 4 + 2][m] = v.z;
            As[k4 * 4 + 3][m] = v.w;
        }
        // load W tile
#pragma unroll
        for (int i = tid; i < BK * BN / 4; i += NT) {
            int k  = i / (BN / 4);
            int n4 = i % (BN / 4);
            *reinterpret_cast<float4*>(&Ws[k][n4 * 4]) =
                *reinterpret_cast<const float4*>(W + (size_t)(k0 + k) * N + n0 + n4 * 4);
        }
        __syncthreads();

#pragma unroll
        for (int k = 0; k < BK; k++) {
            float a[TM], b[TN];
#pragma unroll
            for (int i = 0; i < TM; i++) a[i] = As[k][ty * TM + i];
#pragma unroll
            for (int j = 0; j < TN; j++) b[j] = Ws[k][tx * TN + j];
#pragma unroll
            for (int i = 0; i < TM; i++)
#pragma unroll
                for (int j = 0; j < TN; j++)
                    acc[i][j] = fmaf(a[i], b[j], acc[i][j]);
        }
        __syncthreads();
    }

#pragma unroll
    for (int i = 0; i < TM; i++) {
        int row = m0 + ty * TM + i;
        if (row >= M) continue;
#pragma unroll
        for (int j = 0; j < TN; j++) {
            int col = n0 + tx * TN + j;
            float v = acc[i][j];
            if (BIAS) v += bias[col];
            if (RELU) v = fmaxf(v, 0.0f);
            if (RES)  v += res[(size_t)row * ldres + col];
            C[(size_t)row * ldc + col] = v;
        }
    }
}

// ---------------- small helper kernels ----------------
__global__ void init_kernel(int N)
{
    int i = blockIdx.x * blockDim.x + threadIdx.x;
    if (i < N * 4) { g_smax[i] = -INFINITY; g_den[i] = 0.0f; }
    if (i < N * 256) g_agg[i] = 0.0f;
    if (i < N) g_deg[i] = 1.0f;   // self loop weight 1
}

__global__ void gather_kernel(const int* __restrict__ src, const int* __restrict__ dst, int E)
{
    int idx = blockIdx.x * blockDim.x + threadIdx.x;
    int e = idx >> 6;
    int t = idx & 63;
    if (e >= E) return;
    const float4* xi = reinterpret_cast<const float4*>(g_Xnj) + (size_t)dst[e] * 64;
    const float4* xj = reinterpret_cast<const float4*>(g_Xni) + (size_t)src[e] * 64;
    float4* f = reinterpret_cast<float4*>(g_F) + (size_t)e * 192;
    f[t]        = xi[t];   // x_i  -> F[:,   0:256]
    f[128 + t]  = xj[t];   // x_j  -> F[:, 512:768]  (F[:,256:512] written by Eij GEMM)
}

__device__ __forceinline__ void atomicMaxFloat(float* addr, float v)
{
    if (v >= 0.0f) atomicMax(reinterpret_cast<int*>(addr), __float_as_int(v));
    else           atomicMin(reinterpret_cast<unsigned int*>(addr), __float_as_uint(v));
}

// one warp per edge: scores[e,h] = dot(H2[e,h,:], attn[h,:]); segment max via atomics
__global__ void scores_kernel(const int* __restrict__ dst, int E,
                              const float* __restrict__ attn)
{
    int gid = blockIdx.x * blockDim.x + threadIdx.x;
    int e = gid >> 5;
    int lane = threadIdx.x & 31;
    if (e >= E) return;
    const float4* h2 = reinterpret_cast<const float4*>(g_H2 + (size_t)e * 256);
    const float4* ap = reinterpret_cast<const float4*>(attn);
    float4 v0 = h2[lane * 2], v1 = h2[lane * 2 + 1];
    float4 a0 = ap[lane * 2], a1 = ap[lane * 2 + 1];
    float s = v0.x * a0.x + v0.y * a0.y + v0.z * a0.z + v0.w * a0.w
            + v1.x * a1.x + v1.y * a1.y + v1.z * a1.z + v1.w * a1.w;
    // reduce within 8-lane groups (each group = one head)
    s += __shfl_xor_sync(0xffffffffu, s, 1);
    s += __shfl_xor_sync(0xffffffffu, s, 2);
    s += __shfl_xor_sync(0xffffffffu, s, 4);
    if ((lane & 7) == 0) {
        int h = lane >> 3;
        g_scores[e * 4 + h] = s;
        atomicMaxFloat(&g_smax[(size_t)dst[e] * 4 + h], s);
    }
}

__global__ void ex_kernel(const int* __restrict__ dst, int E)
{
    int i = blockIdx.x * blockDim.x + threadIdx.x;
    if (i >= E * 4) return;
    int e = i >> 2, h = i & 3;
    int d = dst[e];
    float v = expf(g_scores[i] - g_smax[d * 4 + h]);
    g_ex[i] = v;
    atomicAdd(&g_den[d * 4 + h], v);
}

// 64 threads per edge: alpha, attn_weights, and atomic message aggregation
__global__ void agg_kernel(const int* __restrict__ src, const int* __restrict__ dst, int E,
                           const float* __restrict__ linW, float* __restrict__ attn_out)
{
    int idx = blockIdx.x * blockDim.x + threadIdx.x;
    int e = idx >> 6;
    int t = idx & 63;
    if (e >= E) return;
    int d = dst[e], s = src[e];
    int h = t >> 4;
    float alpha = g_ex[e * 4 + h] / g_den[(size_t)d * 4 + h];
    if (t == 0) {
        float aw = 0.0f;
#pragma unroll
        for (int hh = 0; hh < 4; hh++)
            aw += (g_ex[e * 4 + hh] / g_den[(size_t)d * 4 + hh]) * linW[hh];
        attn_out[e] = aw;
    }
    float4 xj = reinterpret_cast<const float4*>(g_Xni + (size_t)s * 256)[t];
    float* dp = g_agg + (size_t)d * 256 + t * 4;
    atomicAdd(dp + 0, xj.x * alpha);
    atomicAdd(dp + 1, xj.y * alpha);
    atomicAdd(dp + 2, xj.z * alpha);
    atomicAdd(dp + 3, xj.w * alpha);
}

__global__ void deg_kernel(const int* __restrict__ src, const int* __restrict__ dst, int E)
{
    int e = blockIdx.x * blockDim.x + threadIdx.x;
    if (e >= E) return;
    int s = src[e];
    if (s != dst[e]) atomicAdd(&g_deg[s], 1.0f);
}

__global__ void dinv_kernel(int N)
{
    int n = blockIdx.x * blockDim.x + threadIdx.x;
    if (n < N) g_dinv[n] = rsqrtf(g_deg[n]);   // deg >= 1 always
}

__global__ void outinit_kernel(const float* __restrict__ gcn_b, float* __restrict__ out, int N)
{
    int i = blockIdx.x * blockDim.x + threadIdx.x;
    if (i >= N * 64) return;
    int n = i >> 6;
    float di = g_dinv[n];
    out[i] = gcn_b[i & 63] + di * di * g_xg[i];
}

__global__ void gcn_scatter_kernel(const int* __restrict__ src, const int* __restrict__ dst,
                                   int E, float* __restrict__ out)
{
    int idx = blockIdx.x * blockDim.x + threadIdx.x;
    int e = idx >> 6;
    int t = idx & 63;
    if (e >= E) return;
    int s = src[e], d = dst[e];
    if (s == d) return;
    float w = g_dinv[s] * g_dinv[d];
    atomicAdd(&out[(size_t)d * 64 + t], w * g_xg[(size_t)s * 64 + t]);
}

// ---------------- launch ----------------
extern "C" void kernel_launch(void* const* d_in, const int* in_sizes, int n_in,
                              void* d_out, int out_size)
{
    const float* node = (const float*)d_in[0];
    const float* edge = (const float*)d_in[1];
    const int*   ei   = (const int*)d_in[2];
    const float* W_ni = (const float*)d_in[3];
    const float* W_nj = (const float*)d_in[4];
    const float* W_eij= (const float*)d_in[5];
    const float* W_nt = (const float*)d_in[6];
    const float* b_nt = (const float*)d_in[7];
    const float* W_et = (const float*)d_in[8];
    const float* b_et = (const float*)d_in[9];
    const float* A0_W = (const float*)d_in[10];
    const float* A0_b = (const float*)d_in[11];
    const float* A1_W = (const float*)d_in[12];
    const float* A1_b = (const float*)d_in[13];
    const float* A2_W = (const float*)d_in[14];
    const float* A2_b = (const float*)d_in[15];
    const float* attn = (const float*)d_in[16];
    const float* Nm0_W= (const float*)d_in[17];
    const float* Nm0_b= (const float*)d_in[18];
    const float* Nm1_W= (const float*)d_in[19];
    const float* Nm1_b= (const float*)d_in[20];
    const float* Nm2_W= (const float*)d_in[21];
    const float* Nm2_b= (const float*)d_in[22];
    const float* Em0_W= (const float*)d_in[23];
    const float* Em0_b= (const float*)d_in[24];
    const float* Em1_W= (const float*)d_in[25];
    const float* Em1_b= (const float*)d_in[26];
    const float* Em2_W= (const float*)d_in[27];
    const float* Em2_b= (const float*)d_in[28];
    const float* linW = (const float*)d_in[29];
    const float* gcnW = (const float*)d_in[30];
    const float* gcnb = (const float*)d_in[31];

    const int N = in_sizes[0] / 256;
    const int E = in_sizes[2] / 2;
    const int* src = ei;
    const int* dst = ei + E;

    float* out      = (float*)d_out;
    float* out_node = out;
    float* out_edge = out + (size_t)N * 64;
    float* out_attn = out_edge + (size_t)E * 64;

    // resolve scratch symbol addresses (capture-safe; no stream ops)
    void* p;
    cudaGetSymbolAddress(&p, g_Xni);   float* pXni = (float*)p;
    cudaGetSymbolAddress(&p, g_Xnj);   float* pXnj = (float*)p;
    cudaGetSymbolAddress(&p, g_Xnt);   float* pXnt = (float*)p;
    cudaGetSymbolAddress(&p, g_Et);    float* pEt  = (float*)p;
    cudaGetSymbolAddress(&p, g_F);     float* pF   = (float*)p;
    cudaGetSymbolAddress(&p, g_H0);    float* pH0  = (float*)p;
    cudaGetSymbolAddress(&p, g_H1);    float* pH1  = (float*)p;
    cudaGetSymbolAddress(&p, g_H2);    float* pH2  = (float*)p;
    cudaGetSymbolAddress(&p, g_EM0);   float* pEM0 = (float*)p;
    cudaGetSymbolAddress(&p, g_EM1);   float* pEM1 = (float*)p;
    cudaGetSymbolAddress(&p, g_agg);   float* pAgg = (float*)p;
    cudaGetSymbolAddress(&p, g_NM0);   float* pNM0 = (float*)p;
    cudaGetSymbolAddress(&p, g_NM1);   float* pNM1 = (float*)p;
    cudaGetSymbolAddress(&p, g_nodeout); float* pNodeOut = (float*)p;
    cudaGetSymbolAddress(&p, g_xg);    float* pXg  = (float*)p;

    const int TPB = 256;
    // 1. init reductions
    init_kernel<<<(N * 256 + TPB - 1) / TPB, TPB>>>(N);

    // 2. node / edge projections
    {
        dim3 g((N + 127) / 128, 2);
        sgemm<128,128,16,8,8,false,false,false><<<g, 256>>>(node, 256, W_ni, nullptr, nullptr, 0, pXni, 256, N, 256, 256);
        sgemm<128,128,16,8,8,false,false,false><<<g, 256>>>(node, 256, W_nj, nullptr, nullptr, 0, pXnj, 256, N, 256, 256);
    }
    {
        dim3 g((N + 127) / 128, 1);
        sgemm<128,64,16,8,4,false,true,false><<<g, 256>>>(node, 256, W_nt, b_nt, nullptr, 0, pXnt, 64, N, 64, 256);
    }
    {
        dim3 g((E + 127) / 128, 2);
        sgemm<128,128,16,8,8,false,false,false><<<g, 256>>>(edge, 128, W_eij, nullptr, nullptr, 0, pF + 256, 768, E, 256, 128);
    }
    {
        dim3 g((E + 127) / 128, 1);
        sgemm<128,64,16,8,4,false,true,false><<<g, 256>>>(edge, 128, W_et, b_et, nullptr, 0, pEt, 64, E, 64, 128);
    }

    // 3. gather x_i / x_j into F
    gather_kernel<<<((size_t)E * 64 + TPB - 1) / TPB, TPB>>>(src, dst, E);

    // 4. attention MLP chain
    {
        dim3 g((E + 127) / 128, 2);
        sgemm<128,128,16,8,8,true,true,false><<<g, 256>>>(pF, 768, A0_W, A0_b, nullptr, 0, pH0, 256, E, 256, 768);
        sgemm<128,128,16,8,8,true,true,false><<<g, 256>>>(pH0, 256, A1_W, A1_b, nullptr, 0, pH1, 256, E, 256, 256);
        sgemm<128,128,16,8,8,true,true,false><<<g, 256>>>(pH1, 256, A2_W, A2_b, nullptr, 0, pH2, 256, E, 256, 256);
    }

    // 5. segment softmax + aggregation
    scores_kernel<<<((size_t)E * 32 + TPB - 1) / TPB, TPB>>>(dst, E, attn);
    ex_kernel<<<((size_t)E * 4 + TPB - 1) / TPB, TPB>>>(dst, E);
    agg_kernel<<<((size_t)E * 64 + TPB - 1) / TPB, TPB>>>(src, dst, E, linW, out_attn);

    // 6. edge MLP (-> edge_out directly)
    {
        dim3 g((E + 127) / 128, 1);
        sgemm<128,64,16,8,4,true,true,false><<<g, 256>>>(pH2, 256, Em0_W, Em0_b, nullptr, 0, pEM0, 64, E, 64, 256);
        sgemm<128,64,16,8,4,true,true,false><<<g, 256>>>(pEM0, 64, Em1_W, Em1_b, nullptr, 0, pEM1, 64, E, 64, 64);
        sgemm<128,64,16,8,4,true,true,true><<<g, 256>>>(pEM1, 64, Em2_W, Em2_b, pEt, 64, out_edge, 64, E, 64, 64);
    }

    // 7. node MLP (+ residual node@W_nt + b_nt)
    {
        dim3 g((N + 127) / 128, 1);
        sgemm<128,64,16,8,4,true,true,false><<<g, 256>>>(pAgg, 256, Nm0_W, Nm0_b, nullptr, 0, pNM0, 64, N, 64, 256);
        sgemm<128,64,16,8,4,true,true,false><<<g, 256>>>(pNM0, 64, Nm1_W, Nm1_b, nullptr, 0, pNM1, 64, N, 64, 64);
        sgemm<128,64,16,8,4,true,true,true><<<g, 256>>>(pNM1, 64, Nm2_W, Nm2_b, pXnt, 64, pNodeOut, 64, N, 64, 64);
    }

    // 8. GCN
    deg_kernel<<<(E + TPB - 1) / TPB, TPB>>>(src, dst, E);
    dinv_kernel<<<(N + TPB - 1) / TPB, TPB>>>(N);
    {
        dim3 g((N + 127) / 128, 1);
        sgemm<128,64,16,8,4,false,false,false><<<g, 256>>>(pNodeOut, 64, gcnW, nullptr, nullptr, 0, pXg, 64, N, 64, 64);
    }
    outinit_kernel<<<(N * 64 + TPB - 1) / TPB, TPB>>>(gcnb, out_node, N);
    gcn_scatter_kernel<<<((size_t)E * 64 + TPB - 1) / TPB, TPB>>>(src, dst, E, out_node);
}

// round 4
// speedup vs baseline: 1.5672x; 1.5672x over previous
#include <cuda_runtime.h>
#include <math.h>

// ---------------- problem constants ----------------
#define MAXN 10000
#define MAXE 160000
// HC = 256, C = 64, H = 4

// ---------------- scratch (device globals; no allocation) ----------------
__device__ float g_Xni[MAXN * 256];
__device__ float g_Xnt[MAXN * 64];
__device__ float g_Et [MAXE * 64];
__device__ float g_Pi [MAXN * 256];
__device__ float g_Pj [MAXN * 256];
__device__ float g_Wcomb[128 * 256];
__device__ float g_Wfold[256 * 256];
__device__ float g_H0 [MAXE * 256];   // P_edge, then (in-place) relu-combined H0
__device__ float g_H1 [MAXE * 256];
__device__ float g_H2 [MAXE * 256];
__device__ float g_EM0[MAXE * 64];
__device__ float g_EM1[MAXE * 64];
__device__ float g_scores[MAXE * 4];
__device__ float g_ex  [MAXE * 4];
__device__ float g_smax[MAXN * 4];
__device__ float g_den [MAXN * 4];
__device__ float g_agg [MAXN * 256];
__device__ float g_NM0 [MAXN * 64];
__device__ float g_NM1 [MAXN * 64];
__device__ float g_nodeout[MAXN * 64];
__device__ float g_deg [MAXN];
__device__ float g_dinv[MAXN];
__device__ float g_xg  [MAXN * 64];

// ---------------- generic tiled SGEMM ----------------
// C[M,N] = epilogue(A[M,K](lda) @ W[K,N]) ; W row-major with leading dim N.
// epilogue: (+bias) -> relu -> (+res)
template<int BM, int BN, int BK, int TM, int TN, bool RELU, bool BIAS, bool RES>
__global__ void __launch_bounds__((BM / TM) * (BN / TN))
sgemm(const float* __restrict__ A, int lda,
      const float* __restrict__ W,
      const float* __restrict__ bias,
      const float* __restrict__ res, int ldres,
      float* __restrict__ C, int ldc,
      int M, int N, int K)
{
    constexpr int NT = (BM / TM) * (BN / TN);
    __shared__ float As[BK][BM + 4];
    __shared__ float Ws[BK][BN];

    const int tid = threadIdx.x;
    const int tx = tid % (BN / TN);
    const int ty = tid / (BN / TN);
    const int m0 = blockIdx.x * BM;
    const int n0 = blockIdx.y * BN;

    float acc[TM][TN];
#pragma unroll
    for (int i = 0; i < TM; i++)
#pragma unroll
        for (int j = 0; j < TN; j++) acc[i][j] = 0.0f;

    for (int k0 = 0; k0 < K; k0 += BK) {
        // load A tile (transposed into shared)
#pragma unroll
        for (int i = tid; i < BM * BK / 4; i += NT) {
            int m  = i / (BK / 4);
            int k4 = i % (BK / 4);
            float4 v = make_float4(0.f, 0.f, 0.f, 0.f);
            int row = m0 + m;
            if (row < M)
                v = *reinterpret_cast<const float4*>(A + (size_t)row * lda + k0 + k4 * 4);
            As[k4 * 4 + 0][m] = v.x;
            As[k4 * 4 + 1][m] = v.y;
            As[k4 * 4 + 2][m] = v.z;
            As[k4 * 4 + 3][m] = v.w;
        }
        // load W tile
#pragma unroll
        for (int i = tid; i < BK * BN / 4; i += NT) {
            int k  = i / (BN / 4);
            int n4 = i % (BN / 4);
            *reinterpret_cast<float4*>(&Ws[k][n4 * 4]) =
                *reinterpret_cast<const float4*>(W + (size_t)(k0 + k) * N + n0 + n4 * 4);
        }
        __syncthreads();

#pragma unroll
        for (int k = 0; k < BK; k++) {
            float a[TM], b[TN];
#pragma unroll
            for (int i = 0; i < TM; i++) a[i] = As[k][ty * TM + i];
#pragma unroll
            for (int j = 0; j < TN; j++) b[j] = Ws[k][tx * TN + j];
#pragma unroll
            for (int i = 0; i < TM; i++)
#pragma unroll
                for (int j = 0; j < TN; j++)
                    acc[i][j] = fmaf(a[i], b[j], acc[i][j]);
        }
        __syncthreads();
    }

#pragma unroll
    for (int i = 0; i < TM; i++) {
        int row = m0 + ty * TM + i;
        if (row >= M) continue;
#pragma unroll
        for (int j = 0; j < TN; j++) {
            int col = n0 + tx * TN + j;
            float v = acc[i][j];
            if (BIAS) v += bias[col];
            if (RELU) v = fmaxf(v, 0.0f);
            if (RES)  v += res[(size_t)row * ldres + col];
            C[(size_t)row * ldc + col] = v;
        }
    }
}

// ---------------- small helper kernels ----------------
__global__ void init_kernel(int N)
{
    int i = blockIdx.x * blockDim.x + threadIdx.x;
    if (i < N * 4) { g_smax[i] = -INFINITY; g_den[i] = 0.0f; }
    if (i < N * 256) g_agg[i] = 0.0f;
    if (i < N) g_deg[i] = 1.0f;   // self loop weight 1
}

// H0[e] = relu(P_edge[e] + P_i[dst[e]] + P_j[src[e]] + A0_b)  (in place on g_H0)
__global__ void combine_kernel(const int* __restrict__ src, const int* __restrict__ dst,
                               int E, const float* __restrict__ A0_b)
{
    int idx = blockIdx.x * blockDim.x + threadIdx.x;
    int e = idx >> 6;
    int t = idx & 63;
    if (e >= E) return;
    int s = src[e], d = dst[e];
    float4* pe = reinterpret_cast<float4*>(g_H0) + (size_t)e * 64 + t;
    float4 v = *pe;
    float4 pi = reinterpret_cast<const float4*>(g_Pi)[(size_t)d * 64 + t];
    float4 pj = reinterpret_cast<const float4*>(g_Pj)[(size_t)s * 64 + t];
    float4 b  = reinterpret_cast<const float4*>(A0_b)[t];
    v.x = fmaxf(v.x + pi.x + pj.x + b.x, 0.0f);
    v.y = fmaxf(v.y + pi.y + pj.y + b.y, 0.0f);
    v.z = fmaxf(v.z + pi.z + pj.z + b.z, 0.0f);
    v.w = fmaxf(v.w + pi.w + pj.w + b.w, 0.0f);
    *pe = v;
}

__device__ __forceinline__ void atomicMaxFloat(float* addr, float v)
{
    if (v >= 0.0f) atomicMax(reinterpret_cast<int*>(addr), __float_as_int(v));
    else           atomicMin(reinterpret_cast<unsigned int*>(addr), __float_as_uint(v));
}

// one warp per edge: scores[e,h] = dot(H2[e,h,:], attn[h,:]); segment max via atomics
__global__ void scores_kernel(const int* __restrict__ dst, int E,
                              const float* __restrict__ attn)
{
    int gid = blockIdx.x * blockDim.x + threadIdx.x;
    int e = gid >> 5;
    int lane = threadIdx.x & 31;
    if (e >= E) return;
    const float4* h2 = reinterpret_cast<const float4*>(g_H2 + (size_t)e * 256);
    const float4* ap = reinterpret_cast<const float4*>(attn);
    float4 v0 = h2[lane * 2], v1 = h2[lane * 2 + 1];
    float4 a0 = ap[lane * 2], a1 = ap[lane * 2 + 1];
    float s = v0.x * a0.x + v0.y * a0.y + v0.z * a0.z + v0.w * a0.w
            + v1.x * a1.x + v1.y * a1.y + v1.z * a1.z + v1.w * a1.w;
    // reduce within 8-lane groups (each group = one head)
    s += __shfl_xor_sync(0xffffffffu, s, 1);
    s += __shfl_xor_sync(0xffffffffu, s, 2);
    s += __shfl_xor_sync(0xffffffffu, s, 4);
    if ((lane & 7) == 0) {
        int h = lane >> 3;
        g_scores[e * 4 + h] = s;
        atomicMaxFloat(&g_smax[(size_t)dst[e] * 4 + h], s);
    }
}

__global__ void ex_kernel(const int* __restrict__ dst, int E)
{
    int i = blockIdx.x * blockDim.x + threadIdx.x;
    if (i >= E * 4) return;
    int e = i >> 2, h = i & 3;
    int d = dst[e];
    float v = expf(g_scores[i] - g_smax[d * 4 + h]);
    g_ex[i] = v;
    atomicAdd(&g_den[d * 4 + h], v);
}

// 64 threads per edge: alpha, attn_weights, and atomic message aggregation
__global__ void agg_kernel(const int* __restrict__ src, const int* __restrict__ dst, int E,
                           const float* __restrict__ linW, float* __restrict__ attn_out)
{
    int idx = blockIdx.x * blockDim.x + threadIdx.x;
    int e = idx >> 6;
    int t = idx & 63;
    if (e >= E) return;
    int d = dst[e], s = src[e];
    int h = t >> 4;
    float alpha = g_ex[e * 4 + h] / g_den[(size_t)d * 4 + h];
    if (t == 0) {
        float aw = 0.0f;
#pragma unroll
        for (int hh = 0; hh < 4; hh++)
            aw += (g_ex[e * 4 + hh] / g_den[(size_t)d * 4 + hh]) * linW[hh];
        attn_out[e] = aw;
    }
    float4 xj = reinterpret_cast<const float4*>(g_Xni + (size_t)s * 256)[t];
    float* dp = g_agg + (size_t)d * 256 + t * 4;
    atomicAdd(dp + 0, xj.x * alpha);
    atomicAdd(dp + 1, xj.y * alpha);
    atomicAdd(dp + 2, xj.z * alpha);
    atomicAdd(dp + 3, xj.w * alpha);
}

__global__ void deg_kernel(const int* __restrict__ src, const int* __restrict__ dst, int E)
{
    int e = blockIdx.x * blockDim.x + threadIdx.x;
    if (e >= E) return;
    int s = src[e];
    if (s != dst[e]) atomicAdd(&g_deg[s], 1.0f);
}

__global__ void dinv_kernel(int N)
{
    int n = blockIdx.x * blockDim.x + threadIdx.x;
    if (n < N) g_dinv[n] = rsqrtf(g_deg[n]);   // deg >= 1 always
}

__global__ void outinit_kernel(const float* __restrict__ gcn_b, float* __restrict__ out, int N)
{
    int i = blockIdx.x * blockDim.x + threadIdx.x;
    if (i >= N * 64) return;
    int n = i >> 6;
    float di = g_dinv[n];
    out[i] = gcn_b[i & 63] + di * di * g_xg[i];
}

__global__ void gcn_scatter_kernel(const int* __restrict__ src, const int* __restrict__ dst,
                                   int E, float* __restrict__ out)
{
    int idx = blockIdx.x * blockDim.x + threadIdx.x;
    int e = idx >> 6;
    int t = idx & 63;
    if (e >= E) return;
    int s = src[e], d = dst[e];
    if (s == d) return;
    float w = g_dinv[s] * g_dinv[d];
    atomicAdd(&out[(size_t)d * 64 + t], w * g_xg[(size_t)s * 64 + t]);
}

// ---------------- launch ----------------
extern "C" void kernel_launch(void* const* d_in, const int* in_sizes, int n_in,
                              void* d_out, int out_size)
{
    const float* node = (const float*)d_in[0];
    const float* edge = (const float*)d_in[1];
    const int*   ei   = (const int*)d_in[2];
    const float* W_ni = (const float*)d_in[3];
    const float* W_nj = (const float*)d_in[4];
    const float* W_eij= (const float*)d_in[5];
    const float* W_nt = (const float*)d_in[6];
    const float* b_nt = (const float*)d_in[7];
    const float* W_et = (const float*)d_in[8];
    const float* b_et = (const float*)d_in[9];
    const float* A0_W = (const float*)d_in[10];
    const float* A0_b = (const float*)d_in[11];
    const float* A1_W = (const float*)d_in[12];
    const float* A1_b = (const float*)d_in[13];
    const float* A2_W = (const float*)d_in[14];
    const float* A2_b = (const float*)d_in[15];
    const float* attn = (const float*)d_in[16];
    const float* Nm0_W= (const float*)d_in[17];
    const float* Nm0_b= (const float*)d_in[18];
    const float* Nm1_W= (const float*)d_in[19];
    const float* Nm1_b= (const float*)d_in[20];
    const float* Nm2_W= (const float*)d_in[21];
    const float* Nm2_b= (const float*)d_in[22];
    const float* Em0_W= (const float*)d_in[23];
    const float* Em0_b= (const float*)d_in[24];
    const float* Em1_W= (const float*)d_in[25];
    const float* Em1_b= (const float*)d_in[26];
    const float* Em2_W= (const float*)d_in[27];
    const float* Em2_b= (const float*)d_in[28];
    const float* linW = (const float*)d_in[29];
    const float* gcnW = (const float*)d_in[30];
    const float* gcnb = (const float*)d_in[31];

    const int N = in_sizes[0] / 256;
    const int E = in_sizes[2] / 2;
    const int* src = ei;
    const int* dst = ei + E;

    float* out      = (float*)d_out;
    float* out_node = out;
    float* out_edge = out + (size_t)N * 64;
    float* out_attn = out_edge + (size_t)E * 64;

    // resolve scratch symbol addresses (capture-safe; no stream ops)
    void* p;
    cudaGetSymbolAddress(&p, g_Xni);   float* pXni = (float*)p;
    cudaGetSymbolAddress(&p, g_Xnt);   float* pXnt = (float*)p;
    cudaGetSymbolAddress(&p, g_Et);    float* pEt  = (float*)p;
    cudaGetSymbolAddress(&p, g_Pi);    float* pPi  = (float*)p;
    cudaGetSymbolAddress(&p, g_Pj);    float* pPj  = (float*)p;
    cudaGetSymbolAddress(&p, g_Wcomb); float* pWcomb = (float*)p;
    cudaGetSymbolAddress(&p, g_Wfold); float* pWfold = (float*)p;
    cudaGetSymbolAddress(&p, g_H0);    float* pH0  = (float*)p;
    cudaGetSymbolAddress(&p, g_H1);    float* pH1  = (float*)p;
    cudaGetSymbolAddress(&p, g_H2);    float* pH2  = (float*)p;
    cudaGetSymbolAddress(&p, g_EM0);   float* pEM0 = (float*)p;
    cudaGetSymbolAddress(&p, g_EM1);   float* pEM1 = (float*)p;
    cudaGetSymbolAddress(&p, g_agg);   float* pAgg = (float*)p;
    cudaGetSymbolAddress(&p, g_NM0);   float* pNM0 = (float*)p;
    cudaGetSymbolAddress(&p, g_NM1);   float* pNM1 = (float*)p;
    cudaGetSymbolAddress(&p, g_nodeout); float* pNodeOut = (float*)p;
    cudaGetSymbolAddress(&p, g_xg);    float* pXg  = (float*)p;

    const int TPB = 256;
    // 1. init reductions
    init_kernel<<<(N * 256 + TPB - 1) / TPB, TPB>>>(N);

    // 2a. weight folds (tiny GEMMs)
    //     Wfold = W_nj @ A0_W[0:256,:]     (x_i path, node level)
    //     Wcomb = W_eij @ A0_W[256:512,:]  (e_ij path, edge level, K=128)
    {
        dim3 g(2, 2);
        sgemm<128,128,16,8,8,false,false,false><<<g, 256>>>(W_nj, 256, A0_W, nullptr, nullptr, 0, pWfold, 256, 256, 256, 256);
    }
    {
        dim3 g(1, 2);
        sgemm<128,128,16,8,8,false,false,false><<<g, 256>>>(W_eij, 256, A0_W + 256 * 256, nullptr, nullptr, 0, pWcomb, 256, 128, 256, 256);
    }

    // 2b. node-level projections
    {
        dim3 g((N + 127) / 128, 2);
        sgemm<128,128,16,8,8,false,false,false><<<g, 256>>>(node, 256, W_ni, nullptr, nullptr, 0, pXni, 256, N, 256, 256);
        sgemm<128,128,16,8,8,false,false,false><<<g, 256>>>(node, 256, pWfold, nullptr, nullptr, 0, pPi, 256, N, 256, 256);
        sgemm<128,128,16,8,8,false,false,false><<<g, 256>>>(pXni, 256, A0_W + 512 * 256, nullptr, nullptr, 0, pPj, 256, N, 256, 256);
    }
    {
        dim3 g((N + 127) / 128, 1);
        sgemm<128,64,16,8,4,false,true,false><<<g, 256>>>(node, 256, W_nt, b_nt, nullptr, 0, pXnt, 64, N, 64, 256);
    }

    // 2c. edge-level projections
    {
        dim3 g((E + 127) / 128, 2);
        sgemm<128,128,16,8,8,false,false,false><<<g, 256>>>(edge, 128, pWcomb, nullptr, nullptr, 0, pH0, 256, E, 256, 128);
    }
    {
        dim3 g((E + 127) / 128, 1);
        sgemm<128,64,16,8,4,false,true,false><<<g, 256>>>(edge, 128, W_et, b_et, nullptr, 0, pEt, 64, E, 64, 128);
    }

    // 3. combine: H0 = relu(P_edge + P_i[dst] + P_j[src] + A0_b)   (in place)
    combine_kernel<<<((size_t)E * 64 + TPB - 1) / TPB, TPB>>>(src, dst, E, A0_b);

    // 4. attention MLP chain
    {
        dim3 g((E + 127) / 128, 2);
        sgemm<128,128,16,8,8,true,true,false><<<g, 256>>>(pH0, 256, A1_W, A1_b, nullptr, 0, pH1, 256, E, 256, 256);
        sgemm<128,128,16,8,8,true,true,false><<<g, 256>>>(pH1, 256, A2_W, A2_b, nullptr, 0, pH2, 256, E, 256, 256);
    }

    // 5. segment softmax + aggregation
    scores_kernel<<<((size_t)E * 32 + TPB - 1) / TPB, TPB>>>(dst, E, attn);
    ex_kernel<<<((size_t)E * 4 + TPB - 1) / TPB, TPB>>>(dst, E);
    agg_kernel<<<((size_t)E * 64 + TPB - 1) / TPB, TPB>>>(src, dst, E, linW, out_attn);

    // 6. edge MLP (-> edge_out directly)
    {
        dim3 g((E + 127) / 128, 1);
        sgemm<128,64,16,8,4,true,true,false><<<g, 256>>>(pH2, 256, Em0_W, Em0_b, nullptr, 0, pEM0, 64, E, 64, 256);
        sgemm<128,64,16,8,4,true,true,false><<<g, 256>>>(pEM0, 64, Em1_W, Em1_b, nullptr, 0, pEM1, 64, E, 64, 64);
        sgemm<128,64,16,8,4,true,true,true><<<g, 256>>>(pEM1, 64, Em2_W, Em2_b, pEt, 64, out_edge, 64, E, 64, 64);
    }

    // 7. node MLP (+ residual node@W_nt + b_nt)
    {
        dim3 g((N + 127) / 128, 1);
        sgemm<128,64,16,8,4,true,true,false><<<g, 256>>>(pAgg, 256, Nm0_W, Nm0_b, nullptr, 0, pNM0, 64, N, 64, 256);
        sgemm<128,64,16,8,4,true,true,false><<<g, 256>>>(pNM0, 64, Nm1_W, Nm1_b, nullptr, 0, pNM1, 64, N, 64, 64);
        sgemm<128,64,16,8,4,true,true,true><<<g, 256>>>(pNM1, 64, Nm2_W, Nm2_b, pXnt, 64, pNodeOut, 64, N, 64, 64);
    }

    // 8. GCN
    deg_kernel<<<(E + TPB - 1) / TPB, TPB>>>(src, dst, E);
    dinv_kernel<<<(N + TPB - 1) / TPB, TPB>>>(N);
    {
        dim3 g((N + 127) / 128, 1);
        sgemm<128,64,16,8,4,false,false,false><<<g, 256>>>(pNodeOut, 64, gcnW, nullptr, nullptr, 0, pXg, 64, N, 64, 64);
    }
    outinit_kernel<<<(N * 64 + TPB - 1) / TPB, TPB>>>(gcnb, out_node, N);
    gcn_scatter_kernel<<<((size_t)E * 64 + TPB - 1) / TPB, TPB>>>(src, dst, E, out_node);
}

// round 6
// speedup vs baseline: 2.5503x; 1.6274x over previous
#include <cuda_runtime.h>
#include <math.h>

// ---------------- problem constants ----------------
#define MAXN 10000
#define MAXE 160000
// HC = 256, C = 64, H = 4

// ---------------- scratch (device globals; no allocation) ----------------
__device__ float g_Xni[MAXN * 256];
__device__ float g_Xnt[MAXN * 64];
__device__ float g_Et [MAXE * 64];
__device__ float g_Pi [MAXN * 256];
__device__ float g_Pj [MAXN * 256];
__device__ float g_Wcomb[128 * 256];
__device__ float g_Wfold[256 * 256];
__device__ float g_H0 [MAXE * 256];   // P_edge, then (in-place) relu-combined H0
__device__ float g_H1 [MAXE * 256];
__device__ float g_H2 [MAXE * 256];
__device__ float g_EM0[MAXE * 64];
__device__ float g_EM1[MAXE * 64];
__device__ float g_scores[MAXE * 4];
__device__ float g_ex  [MAXE * 4];
__device__ float g_smax[MAXN * 4];
__device__ float g_den [MAXN * 4];
__device__ float g_agg [MAXN * 256];
__device__ float g_NM0 [MAXN * 64];
__device__ float g_NM1 [MAXN * 64];
__device__ float g_nodeout[MAXN * 64];
__device__ float g_deg [MAXN];
__device__ float g_dinv[MAXN];
__device__ float g_xg  [MAXN * 64];
// transposed tf32 weights [N,K] (K contiguous)
__device__ float g_BtA1  [256 * 256];
__device__ float g_BtA2  [256 * 256];
__device__ float g_BtComb[256 * 128];
__device__ float g_BtEm0 [64 * 256];
__device__ float g_BtNi  [256 * 256];
__device__ float g_BtFold[256 * 256];
__device__ float g_BtPj  [256 * 256];

static __device__ __forceinline__ float to_tf32(float x) {
    float r; asm("cvt.rna.tf32.f32 %0, %1;" : "=f"(r) : "f"(x)); return r;
}
static __device__ __forceinline__ void mma_tf32(float* d, const unsigned* a, const unsigned* b) {
    asm volatile(
        "mma.sync.aligned.m16n8k8.row.col.f32.tf32.tf32.f32 "
        "{%0,%1,%2,%3}, {%4,%5,%6,%7}, {%8,%9}, {%0,%1,%2,%3};"
        : "+f"(d[0]), "+f"(d[1]), "+f"(d[2]), "+f"(d[3])
        : "r"(a[0]), "r"(a[1]), "r"(a[2]), "r"(a[3]), "r"(b[0]), "r"(b[1]));
}

// ---------------- tf32 warp-MMA GEMM ----------------
// C[M, ldc(part)] = epi(A[M,K] @ Bt[n0:n0+BN, K]^T)
// A fp32 row-major (rounded to tf32 on smem store); Bt pre-rounded tf32 [Ntot,K].
// Block: 256 thr = 8 warps (4 m x 2 n); BM=128, BN in {64,128}, BK=16.
template<int BN, bool BIASRELU>
__global__ void __launch_bounds__(256)
mma_gemm(const float* __restrict__ A, const float* __restrict__ Bt,
         const float* __restrict__ bias, float* __restrict__ C,
         int M, int K, int ldc)
{
    constexpr int NF = BN / 16;     // n-frags per warp (warp n-tile = BN/2)
    constexpr int WN = BN / 2;
    __shared__ float As[128][20];
    __shared__ float Bs[BN][20];

    const int tid = threadIdx.x;
    const int lane = tid & 31, wid = tid >> 5;
    const int wm = wid & 3, wn = wid >> 2;
    const int m0 = blockIdx.x * 128;
    const int n0 = blockIdx.y * BN;
    const int lq = lane >> 2;      // 0..7
    const int lc = lane & 3;       // 0..3

    float acc[2][NF][4];
#pragma unroll
    for (int i = 0; i < 2; i++)
#pragma unroll
        for (int j = 0; j < NF; j++)
#pragma unroll
            for (int q = 0; q < 4; q++) acc[i][j][q] = 0.0f;

    for (int k0 = 0; k0 < K; k0 += 16) {
        // ---- load A tile [128,16] (cvt to tf32) ----
#pragma unroll
        for (int i = tid; i < 512; i += 256) {
            int m = i >> 2, q = i & 3;
            float4 v = make_float4(0.f, 0.f, 0.f, 0.f);
            int row = m0 + m;
            if (row < M) v = *reinterpret_cast<const float4*>(A + (size_t)row * K + k0 + q * 4);
            v.x = to_tf32(v.x); v.y = to_tf32(v.y); v.z = to_tf32(v.z); v.w = to_tf32(v.w);
            *reinterpret_cast<float4*>(&As[m][q * 4]) = v;
        }
        // ---- load B tile [BN,16] (pre-rounded) ----
#pragma unroll
        for (int i = tid; i < BN * 4; i += 256) {
            int n = i >> 2, q = i & 3;
            float4 v = *reinterpret_cast<const float4*>(Bt + (size_t)(n0 + n) * K + k0 + q * 4);
            *reinterpret_cast<float4*>(&Bs[n][q * 4]) = v;
        }
        __syncthreads();

#pragma unroll
        for (int kk = 0; kk < 16; kk += 8) {
            unsigned a[2][4];
#pragma unroll
            for (int mf = 0; mf < 2; mf++) {
                int m = wm * 32 + mf * 16 + lq;
                a[mf][0] = __float_as_uint(As[m][kk + lc]);
                a[mf][1] = __float_as_uint(As[m + 8][kk + lc]);
                a[mf][2] = __float_as_uint(As[m][kk + 4 + lc]);
                a[mf][3] = __float_as_uint(As[m + 8][kk + 4 + lc]);
            }
            unsigned b[NF][2];
#pragma unroll
            for (int nf = 0; nf < NF; nf++) {
                int n = wn * WN + nf * 8 + lq;
                b[nf][0] = __float_as_uint(Bs[n][kk + lc]);
                b[nf][1] = __float_as_uint(Bs[n][kk + 4 + lc]);
            }
#pragma unroll
            for (int mf = 0; mf < 2; mf++)
#pragma unroll
                for (int nf = 0; nf < NF; nf++)
                    mma_tf32(acc[mf][nf], a[mf], b[nf]);
        }
        __syncthreads();
    }

    // ---- epilogue ----
#pragma unroll
    for (int mf = 0; mf < 2; mf++) {
#pragma unroll
        for (int nf = 0; nf < NF; nf++) {
            int row = m0 + wm * 32 + mf * 16 + lq;
            int col = n0 + wn * WN + nf * 8 + lc * 2;
            float2 bv = make_float2(0.f, 0.f);
            if (BIASRELU) bv = *reinterpret_cast<const float2*>(bias + col);
            float2 v0 = make_float2(acc[mf][nf][0], acc[mf][nf][1]);
            float2 v1 = make_float2(acc[mf][nf][2], acc[mf][nf][3]);
            if (BIASRELU) {
                v0.x = fmaxf(v0.x + bv.x, 0.f); v0.y = fmaxf(v0.y + bv.y, 0.f);
                v1.x = fmaxf(v1.x + bv.x, 0.f); v1.y = fmaxf(v1.y + bv.y, 0.f);
            }
            if (row < M)
                *reinterpret_cast<float2*>(C + (size_t)row * ldc + col) = v0;
            if (row + 8 < M)
                *reinterpret_cast<float2*>(C + (size_t)(row + 8) * ldc + col) = v1;
        }
    }
}

// transpose W[K,N] -> Bt[N,K], rounded to tf32
__global__ void transpose_tf32(const float* __restrict__ W, float* __restrict__ Bt, int K, int Nd)
{
    int i = blockIdx.x * blockDim.x + threadIdx.x;
    if (i >= K * Nd) return;
    int n = i / K, k = i % K;
    Bt[i] = to_tf32(W[(size_t)k * Nd + n]);
}

// ---------------- generic tiled fp32 SGEMM (small GEMMs) ----------------
template<int BM, int BN, int BK, int TM, int TN, bool RELU, bool BIAS, bool RES>
__global__ void __launch_bounds__((BM / TM) * (BN / TN))
sgemm(const float* __restrict__ A, int lda,
      const float* __restrict__ W,
      const float* __restrict__ bias,
      const float* __restrict__ res, int ldres,
      float* __restrict__ C, int ldc,
      int M, int N, int K)
{
    constexpr int NT = (BM / TM) * (BN / TN);
    __shared__ float As[BK][BM + 4];
    __shared__ float Ws[BK][BN];

    const int tid = threadIdx.x;
    const int tx = tid % (BN / TN);
    const int ty = tid / (BN / TN);
    const int m0 = blockIdx.x * BM;
    const int n0 = blockIdx.y * BN;

    float acc[TM][TN];
#pragma unroll
    for (int i = 0; i < TM; i++)
#pragma unroll
        for (int j = 0; j < TN; j++) acc[i][j] = 0.0f;

    for (int k0 = 0; k0 < K; k0 += BK) {
#pragma unroll
        for (int i = tid; i < BM * BK / 4; i += NT) {
            int m  = i / (BK / 4);
            int k4 = i % (BK / 4);
            float4 v = make_float4(0.f, 0.f, 0.f, 0.f);
            int row = m0 + m;
            if (row < M)
                v = *reinterpret_cast<const float4*>(A + (size_t)row * lda + k0 + k4 * 4);
            As[k4 * 4 + 0][m] = v.x;
            As[k4 * 4 + 1][m] = v.y;
            As[k4 * 4 + 2][m] = v.z;
            As[k4 * 4 + 3][m] = v.w;
        }
#pragma unroll
        for (int i = tid; i < BK * BN / 4; i += NT) {
            int k  = i / (BN / 4);
            int n4 = i % (BN / 4);
            *reinterpret_cast<float4*>(&Ws[k][n4 * 4]) =
                *reinterpret_cast<const float4*>(W + (size_t)(k0 + k) * N + n0 + n4 * 4);
        }
        __syncthreads();

#pragma unroll
        for (int k = 0; k < BK; k++) {
            float a[TM], b[TN];
#pragma unroll
            for (int i = 0; i < TM; i++) a[i] = As[k][ty * TM + i];
#pragma unroll
            for (int j = 0; j < TN; j++) b[j] = Ws[k][tx * TN + j];
#pragma unroll
            for (int i = 0; i < TM; i++)
#pragma unroll
                for (int j = 0; j < TN; j++)
                    acc[i][j] = fmaf(a[i], b[j], acc[i][j]);
        }
        __syncthreads();
    }

#pragma unroll
    for (int i = 0; i < TM; i++) {
        int row = m0 + ty * TM + i;
        if (row >= M) continue;
#pragma unroll
        for (int j = 0; j < TN; j++) {
            int col = n0 + tx * TN + j;
            float v = acc[i][j];
            if (BIAS) v += bias[col];
            if (RELU) v = fmaxf(v, 0.0f);
            if (RES)  v += res[(size_t)row * ldres + col];
            C[(size_t)row * ldc + col] = v;
        }
    }
}

// ---------------- small helper kernels ----------------
__global__ void init_kernel(int N)
{
    int i = blockIdx.x * blockDim.x + threadIdx.x;
    if (i < N * 4) { g_smax[i] = -INFINITY; g_den[i] = 0.0f; }
    if (i < N * 256) g_agg[i] = 0.0f;
    if (i < N) g_deg[i] = 1.0f;   // self loop weight 1
}

// H0[e] = relu(P_edge[e] + P_i[dst[e]] + P_j[src[e]] + A0_b)  (in place on g_H0)
__global__ void combine_kernel(const int* __restrict__ src, const int* __restrict__ dst,
                               int E, const float* __restrict__ A0_b)
{
    int idx = blockIdx.x * blockDim.x + threadIdx.x;
    int e = idx >> 6;
    int t = idx & 63;
    if (e >= E) return;
    int s = src[e], d = dst[e];
    float4* pe = reinterpret_cast<float4*>(g_H0) + (size_t)e * 64 + t;
    float4 v = *pe;
    float4 pi = reinterpret_cast<const float4*>(g_Pi)[(size_t)d * 64 + t];
    float4 pj = reinterpret_cast<const float4*>(g_Pj)[(size_t)s * 64 + t];
    float4 b  = reinterpret_cast<const float4*>(A0_b)[t];
    v.x = fmaxf(v.x + pi.x + pj.x + b.x, 0.0f);
    v.y = fmaxf(v.y + pi.y + pj.y + b.y, 0.0f);
    v.z = fmaxf(v.z + pi.z + pj.z + b.z, 0.0f);
    v.w = fmaxf(v.w + pi.w + pj.w + b.w, 0.0f);
    *pe = v;
}

__device__ __forceinline__ void atomicMaxFloat(float* addr, float v)
{
    if (v >= 0.0f) atomicMax(reinterpret_cast<int*>(addr), __float_as_int(v));
    else           atomicMin(reinterpret_cast<unsigned int*>(addr), __float_as_uint(v));
}

__global__ void scores_kernel(const int* __restrict__ dst, int E,
                              const float* __restrict__ attn)
{
    int gid = blockIdx.x * blockDim.x + threadIdx.x;
    int e = gid >> 5;
    int lane = threadIdx.x & 31;
    if (e >= E) return;
    const float4* h2 = reinterpret_cast<const float4*>(g_H2 + (size_t)e * 256);
    const float4* ap = reinterpret_cast<const float4*>(attn);
    float4 v0 = h2[lane * 2], v1 = h2[lane * 2 + 1];
    float4 a0 = ap[lane * 2], a1 = ap[lane * 2 + 1];
    float s = v0.x * a0.x + v0.y * a0.y + v0.z * a0.z + v0.w * a0.w
            + v1.x * a1.x + v1.y * a1.y + v1.z * a1.z + v1.w * a1.w;
    s += __shfl_xor_sync(0xffffffffu, s, 1);
    s += __shfl_xor_sync(0xffffffffu, s, 2);
    s += __shfl_xor_sync(0xffffffffu, s, 4);
    if ((lane & 7) == 0) {
        int h = lane >> 3;
        g_scores[e * 4 + h] = s;
        atomicMaxFloat(&g_smax[(size_t)dst[e] * 4 + h], s);
    }
}

__global__ void ex_kernel(const int* __restrict__ dst, int E)
{
    int i = blockIdx.x * blockDim.x + threadIdx.x;
    if (i >= E * 4) return;
    int e = i >> 2, h = i & 3;
    int d = dst[e];
    float v = expf(g_scores[i] - g_smax[d * 4 + h]);
    g_ex[i] = v;
    atomicAdd(&g_den[d * 4 + h], v);
}

__global__ void agg_kernel(const int* __restrict__ src, const int* __restrict__ dst, int E,
                           const float* __restrict__ linW, float* __restrict__ attn_out)
{
    int idx = blockIdx.x * blockDim.x + threadIdx.x;
    int e = idx >> 6;
    int t = idx & 63;
    if (e >= E) return;
    int d = dst[e], s = src[e];
    int h = t >> 4;
    float alpha = g_ex[e * 4 + h] / g_den[(size_t)d * 4 + h];
    if (t == 0) {
        float aw = 0.0f;
#pragma unroll
        for (int hh = 0; hh < 4; hh++)
            aw += (g_ex[e * 4 + hh] / g_den[(size_t)d * 4 + hh]) * linW[hh];
        attn_out[e] = aw;
    }
    float4 xj = reinterpret_cast<const float4*>(g_Xni + (size_t)s * 256)[t];
    float* dp = g_agg + (size_t)d * 256 + t * 4;
    atomicAdd(dp + 0, xj.x * alpha);
    atomicAdd(dp + 1, xj.y * alpha);
    atomicAdd(dp + 2, xj.z * alpha);
    atomicAdd(dp + 3, xj.w * alpha);
}

__global__ void deg_kernel(const int* __restrict__ src, const int* __restrict__ dst, int E)
{
    int e = blockIdx.x * blockDim.x + threadIdx.x;
    if (e >= E) return;
    int s = src[e];
    if (s != dst[e]) atomicAdd(&g_deg[s], 1.0f);
}

__global__ void dinv_kernel(int N)
{
    int n = blockIdx.x * blockDim.x + threadIdx.x;
    if (n < N) g_dinv[n] = rsqrtf(g_deg[n]);
}

__global__ void outinit_kernel(const float* __restrict__ gcn_b, float* __restrict__ out, int N)
{
    int i = blockIdx.x * blockDim.x + threadIdx.x;
    if (i >= N * 64) return;
    int n = i >> 6;
    float di = g_dinv[n];
    out[i] = gcn_b[i & 63] + di * di * g_xg[i];
}

__global__ void gcn_scatter_kernel(const int* __restrict__ src, const int* __restrict__ dst,
                                   int E, float* __restrict__ out)
{
    int idx = blockIdx.x * blockDim.x + threadIdx.x;
    int e = idx >> 6;
    int t = idx & 63;
    if (e >= E) return;
    int s = src[e], d = dst[e];
    if (s == d) return;
    float w = g_dinv[s] * g_dinv[d];
    atomicAdd(&out[(size_t)d * 64 + t], w * g_xg[(size_t)s * 64 + t]);
}

// ---------------- launch ----------------
extern "C" void kernel_launch(void* const* d_in, const int* in_sizes, int n_in,
                              void* d_out, int out_size)
{
    const float* node = (const float*)d_in[0];
    const float* edge = (const float*)d_in[1];
    const int*   ei   = (const int*)d_in[2];
    const float* W_ni = (const float*)d_in[3];
    const float* W_nj = (const float*)d_in[4];
    const float* W_eij= (const float*)d_in[5];
    const float* W_nt = (const float*)d_in[6];
    const float* b_nt = (const float*)d_in[7];
    const float* W_et = (const float*)d_in[8];
    const float* b_et = (const float*)d_in[9];
    const float* A0_W = (const float*)d_in[10];
    const float* A0_b = (const float*)d_in[11];
    const float* A1_W = (const float*)d_in[12];
    const float* A1_b = (const float*)d_in[13];
    const float* A2_W = (const float*)d_in[14];
    const float* A2_b = (const float*)d_in[15];
    const float* attn = (const float*)d_in[16];
    const float* Nm0_W= (const float*)d_in[17];
    const float* Nm0_b= (const float*)d_in[18];
    const float* Nm1_W= (const float*)d_in[19];
    const float* Nm1_b= (const float*)d_in[20];
    const float* Nm2_W= (const float*)d_in[21];
    const float* Nm2_b= (const float*)d_in[22];
    const float* Em0_W= (const float*)d_in[23];
    const float* Em0_b= (const float*)d_in[24];
    const float* Em1_W= (const float*)d_in[25];
    const float* Em1_b= (const float*)d_in[26];
    const float* Em2_W= (const float*)d_in[27];
    const float* Em2_b= (const float*)d_in[28];
    const float* linW = (const float*)d_in[29];
    const float* gcnW = (const float*)d_in[30];
    const float* gcnb = (const float*)d_in[31];

    const int N = in_sizes[0] / 256;
    const int E = in_sizes[2] / 2;
    const int* src = ei;
    const int* dst = ei + E;

    float* out      = (float*)d_out;
    float* out_node = out;
    float* out_edge = out + (size_t)N * 64;
    float* out_attn = out_edge + (size_t)E * 64;

    void* p;
    cudaGetSymbolAddress(&p, g_Xni);   float* pXni = (float*)p;
    cudaGetSymbolAddress(&p, g_Xnt);   float* pXnt = (float*)p;
    cudaGetSymbolAddress(&p, g_Et);    float* pEt  = (float*)p;
    cudaGetSymbolAddress(&p, g_Pi);    float* pPi  = (float*)p;
    cudaGetSymbolAddress(&p, g_Pj);    float* pPj  = (float*)p;
    cudaGetSymbolAddress(&p, g_Wcomb); float* pWcomb = (float*)p;
    cudaGetSymbolAddress(&p, g_Wfold); float* pWfold = (float*)p;
    cudaGetSymbolAddress(&p, g_H0);    float* pH0  = (float*)p;
    cudaGetSymbolAddress(&p, g_H1);    float* pH1  = (float*)p;
    cudaGetSymbolAddress(&p, g_H2);    float* pH2  = (float*)p;
    cudaGetSymbolAddress(&p, g_EM0);   float* pEM0 = (float*)p;
    cudaGetSymbolAddress(&p, g_EM1);   float* pEM1 = (float*)p;
    cudaGetSymbolAddress(&p, g_agg);   float* pAgg = (float*)p;
    cudaGetSymbolAddress(&p, g_NM0);   float* pNM0 = (float*)p;
    cudaGetSymbolAddress(&p, g_NM1);   float* pNM1 = (float*)p;
    cudaGetSymbolAddress(&p, g_nodeout); float* pNodeOut = (float*)p;
    cudaGetSymbolAddress(&p, g_xg);    float* pXg  = (float*)p;
    cudaGetSymbolAddress(&p, g_BtA1);   float* pBtA1 = (float*)p;
    cudaGetSymbolAddress(&p, g_BtA2);   float* pBtA2 = (float*)p;
    cudaGetSymbolAddress(&p, g_BtComb); float* pBtComb = (float*)p;
    cudaGetSymbolAddress(&p, g_BtEm0);  float* pBtEm0 = (float*)p;
    cudaGetSymbolAddress(&p, g_BtNi);   float* pBtNi = (float*)p;
    cudaGetSymbolAddress(&p, g_BtFold); float* pBtFold = (float*)p;
    cudaGetSymbolAddress(&p, g_BtPj);   float* pBtPj = (float*)p;

    const int TPB = 256;
    const int MT_E = (E + 127) / 128;   // edge m-tiles
    const int MT_N = (N + 127) / 128;   // node m-tiles

    // 1. init reductions
    init_kernel<<<(N * 256 + TPB - 1) / TPB, TPB>>>(N);

    // 2a. weight folds (fp32)
    {
        dim3 g(2, 2);
        sgemm<128,128,16,8,8,false,false,false><<<g, 256>>>(W_nj, 256, A0_W, nullptr, nullptr, 0, pWfold, 256, 256, 256, 256);
    }
    {
        dim3 g(1, 2);
        sgemm<128,128,16,8,8,false,false,false><<<g, 256>>>(W_eij, 256, A0_W + 256 * 256, nullptr, nullptr, 0, pWcomb, 256, 128, 256, 256);
    }

    // 2b. transposed tf32 weight copies
    transpose_tf32<<<256, 256>>>(A1_W, pBtA1, 256, 256);
    transpose_tf32<<<256, 256>>>(A2_W, pBtA2, 256, 256);
    transpose_tf32<<<128, 256>>>(pWcomb, pBtComb, 128, 256);
    transpose_tf32<<<64, 256>>>(Em0_W, pBtEm0, 256, 64);
    transpose_tf32<<<256, 256>>>(W_ni, pBtNi, 256, 256);
    transpose_tf32<<<256, 256>>>(pWfold, pBtFold, 256, 256);
    transpose_tf32<<<256, 256>>>(A0_W + 512 * 256, pBtPj, 256, 256);

    // 2c. node-level projections (tf32 mma)
    {
        dim3 g(MT_N, 2);
        mma_gemm<128, false><<<g, 256>>>(node, pBtNi,   nullptr, pXni, N, 256, 256);
        mma_gemm<128, false><<<g, 256>>>(node, pBtFold, nullptr, pPi,  N, 256, 256);
        mma_gemm<128, false><<<g, 256>>>(pXni, pBtPj,   nullptr, pPj,  N, 256, 256);
    }
    {
        dim3 g(MT_N, 1);
        sgemm<128,64,16,8,4,false,true,false><<<g, 256>>>(node, 256, W_nt, b_nt, nullptr, 0, pXnt, 64, N, 64, 256);
    }

    // 2d. edge projections: P_edge (tf32 mma) and Et (fp32)
    {
        dim3 g(MT_E, 2);
        mma_gemm<128, false><<<g, 256>>>(edge, pBtComb, nullptr, pH0, E, 128, 256);
    }
    {
        dim3 g(MT_E, 1);
        sgemm<128,64,16,8,4,false,true,false><<<g, 256>>>(edge, 128, W_et, b_et, nullptr, 0, pEt, 64, E, 64, 128);
    }

    // 3. combine: H0 = relu(P_edge + P_i[dst] + P_j[src] + A0_b)
    combine_kernel<<<((size_t)E * 64 + TPB - 1) / TPB, TPB>>>(src, dst, E, A0_b);

    // 4. attention MLP chain (tf32 mma)
    {
        dim3 g(MT_E, 2);
        mma_gemm<128, true><<<g, 256>>>(pH0, pBtA1, A1_b, pH1, E, 256, 256);
        mma_gemm<128, true><<<g, 256>>>(pH1, pBtA2, A2_b, pH2, E, 256, 256);
    }

    // 5. segment softmax + aggregation
    scores_kernel<<<((size_t)E * 32 + TPB - 1) / TPB, TPB>>>(dst, E, attn);
    ex_kernel<<<((size_t)E * 4 + TPB - 1) / TPB, TPB>>>(dst, E);
    agg_kernel<<<((size_t)E * 64 + TPB - 1) / TPB, TPB>>>(src, dst, E, linW, out_attn);

    // 6. edge MLP: Em0 (tf32 mma), Em1/Em2 (fp32)
    {
        dim3 g(MT_E, 1);
        mma_gemm<64, true><<<g, 256>>>(pH2, pBtEm0, Em0_b, pEM0, E, 256, 64);
        sgemm<128,64,16,8,4,true,true,false><<<g, 256>>>(pEM0, 64, Em1_W, Em1_b, nullptr, 0, pEM1, 64, E, 64, 64);
        sgemm<128,64,16,8,4,true,true,true><<<g, 256>>>(pEM1, 64, Em2_W, Em2_b, pEt, 64, out_edge, 64, E, 64, 64);
    }

    // 7. node MLP (+ residual node@W_nt + b_nt)
    {
        dim3 g(MT_N, 1);
        sgemm<128,64,16,8,4,true,true,false><<<g, 256>>>(pAgg, 256, Nm0_W, Nm0_b, nullptr, 0, pNM0, 64, N, 64, 256);
        sgemm<128,64,16,8,4,true,true,false><<<g, 256>>>(pNM0, 64, Nm1_W, Nm1_b, nullptr, 0, pNM1, 64, N, 64, 64);
        sgemm<128,64,16,8,4,true,true,true><<<g, 256>>>(pNM1, 64, Nm2_W, Nm2_b, pXnt, 64, pNodeOut, 64, N, 64, 64);
    }

    // 8. GCN
    deg_kernel<<<(E + TPB - 1) / TPB, TPB>>>(src, dst, E);
    dinv_kernel<<<(N + TPB - 1) / TPB, TPB>>>(N);
    {
        dim3 g(MT_N, 1);
        sgemm<128,64,16,8,4,false,false,false><<<g, 256>>>(pNodeOut, 64, gcnW, nullptr, nullptr, 0, pXg, 64, N, 64, 64);
    }
    outinit_kernel<<<(N * 64 + TPB - 1) / TPB, TPB>>>(gcnb, out_node, N);
    gcn_scatter_kernel<<<((size_t)E * 64 + TPB - 1) / TPB, TPB>>>(src, dst, E, out_node);
}

// round 7
// speedup vs baseline: 2.8057x; 1.1001x over previous
#include <cuda_runtime.h>
#include <math.h>

// ---------------- problem constants ----------------
#define MAXN 10000
#define MAXE 160000
// HC = 256, C = 64, H = 4

// ---------------- scratch (device globals; no allocation) ----------------
__device__ float g_Xni[MAXN * 256];
__device__ float g_Xnt[MAXN * 64];
__device__ float g_Et [MAXE * 64];
__device__ float g_Pi [MAXN * 256];
__device__ float g_Pj [MAXN * 256];
__device__ float g_Wcomb[128 * 256];
__device__ float g_Wfold[256 * 256];
__device__ float g_scores[MAXE * 4];
__device__ float g_ex  [MAXE * 4];
__device__ float g_smax[MAXN * 4];
__device__ float g_den [MAXN * 4];
__device__ float g_agg [MAXN * 256];
__device__ float g_NM0 [MAXN * 64];
__device__ float g_NM1 [MAXN * 64];
__device__ float g_nodeout[MAXN * 64];
__device__ float g_deg [MAXN];
__device__ float g_dinv[MAXN];
__device__ float g_xg  [MAXN * 64];
// transposed tf32 weights [N,K] (K contiguous)
__device__ float g_BtA1  [256 * 256];
__device__ float g_BtA2  [256 * 256];
__device__ float g_BtComb[256 * 128];
__device__ float g_BtEm0 [64 * 256];
__device__ float g_BtEm1 [64 * 64];
__device__ float g_BtEm2 [64 * 64];
__device__ float g_BtNi  [256 * 256];
__device__ float g_BtFold[256 * 256];
__device__ float g_BtPj  [256 * 256];

static __device__ __forceinline__ float to_tf32(float x) {
    float r; asm("cvt.rna.tf32.f32 %0, %1;" : "=f"(r) : "f"(x)); return r;
}
static __device__ __forceinline__ void mma_tf32(float* d, const unsigned* a, const unsigned* b) {
    asm volatile(
        "mma.sync.aligned.m16n8k8.row.col.f32.tf32.tf32.f32 "
        "{%0,%1,%2,%3}, {%4,%5,%6,%7}, {%8,%9}, {%0,%1,%2,%3};"
        : "+f"(d[0]), "+f"(d[1]), "+f"(d[2]), "+f"(d[3])
        : "r"(a[0]), "r"(a[1]), "r"(a[2]), "r"(a[3]), "r"(b[0]), "r"(b[1]));
}
static __device__ __forceinline__ unsigned smem_u32(const void* p) {
    unsigned a;
    asm("{ .reg .u64 t; cvta.to.shared.u64 t, %1; cvt.u32.u64 %0, t; }" : "=r"(a) : "l"(p));
    return a;
}
static __device__ __forceinline__ void cpa16(unsigned dst, const float* src) {
    asm volatile("cp.async.ca.shared.global [%0], [%1], 16;" :: "r"(dst), "l"(src));
}
static __device__ __forceinline__ void atomicAdd4(float4* a, float4 v) {
#if !defined(__CUDA_ARCH__) || __CUDA_ARCH__ >= 900
    atomicAdd(a, v);
#else
    atomicAdd(&a->x, v.x); atomicAdd(&a->y, v.y);
    atomicAdd(&a->z, v.z); atomicAdd(&a->w, v.w);
#endif
}
__device__ __forceinline__ void atomicMaxFloat(float* addr, float v)
{
    if (v >= 0.0f) atomicMax(reinterpret_cast<int*>(addr), __float_as_int(v));
    else           atomicMin(reinterpret_cast<unsigned int*>(addr), __float_as_uint(v));
}

// ---------------- fused edge-chain building block ----------------
// acc[2][NF][4] = sA[64,K](stride 260) @ Bt[NTOT,K]^T  for this warp.
// Weights streamed global->smem via cp.async, double-buffered 16-wide K chunks.
// 8 warps: wm = wid&1 (2 x 32 rows), wn = wid>>1 (4 n-strips of NF*8).
template<int NF>
static __device__ __forceinline__ void gemm_stage(
    const float* __restrict__ sA, const float* __restrict__ Bt, int K,
    float* __restrict__ sW, unsigned sWu, int tid, float (&acc)[2][NF][4])
{
    constexpr int NTOT = NF * 32;
    const int lane = tid & 31, wid = tid >> 5;
    const int wm = wid & 1, wn = wid >> 1;
    const int lq = lane >> 2, lc = lane & 3;
    const int NC = K >> 4;

#pragma unroll
    for (int i = 0; i < 2; i++)
#pragma unroll
        for (int j = 0; j < NF; j++)
#pragma unroll
            for (int q = 0; q < 4; q++) acc[i][j][q] = 0.f;

    // preload chunk 0 into buf 0
    for (int i = tid; i < NTOT * 4; i += 256) {
        int n = i >> 2, q = i & 3;
        cpa16(sWu + (unsigned)(n * 20 + q * 4) * 4u, Bt + (size_t)n * K + q * 4);
    }
    asm volatile("cp.async.commit_group;");

    for (int c = 0; c < NC; c++) {
        if (c + 1 < NC) {
            unsigned boff = (unsigned)(((c + 1) & 1) * NTOT * 20) * 4u;
            for (int i = tid; i < NTOT * 4; i += 256) {
                int n = i >> 2, q = i & 3;
                cpa16(sWu + boff + (unsigned)(n * 20 + q * 4) * 4u,
                      Bt + (size_t)n * K + (c + 1) * 16 + q * 4);
            }
            asm volatile("cp.async.commit_group;");
            asm volatile("cp.async.wait_group 1;");
        } else {
            asm volatile("cp.async.wait_group 0;");
        }
        __syncthreads();
        const float* B = sW + (c & 1) * NTOT * 20;
        const int kb = c * 16;
#pragma unroll
        for (int kk = 0; kk < 16; kk += 8) {
            unsigned a[2][4];
#pragma unroll
            for (int mf = 0; mf < 2; mf++) {
                int m = wm * 32 + mf * 16 + lq;
                a[mf][0] = __float_as_uint(sA[m * 260 + kb + kk + lc]);
                a[mf][1] = __float_as_uint(sA[(m + 8) * 260 + kb + kk + lc]);
                a[mf][2] = __float_as_uint(sA[m * 260 + kb + kk + 4 + lc]);
                a[mf][3] = __float_as_uint(sA[(m + 8) * 260 + kb + kk + 4 + lc]);
            }
#pragma unroll
            for (int nf = 0; nf < NF; nf++) {
                unsigned b[2];
                int n = wn * (NF * 8) + nf * 8 + lq;
                b[0] = __float_as_uint(B[n * 20 + kk + lc]);
                b[1] = __float_as_uint(B[n * 20 + kk + 4 + lc]);
#pragma unroll
                for (int mf = 0; mf < 2; mf++)
                    mma_tf32(acc[mf][nf], a[mf], b);
            }
        }
        __syncthreads();
    }
}

// ---------------- fused edge mega-kernel ----------------
// Per 64-edge tile: comb-GEMM(+gather/relu) -> A1 -> A2(+scores) -> Em0 -> Em1
// -> Em2(+Et residual -> out_edge). All intermediates live in smem.
__global__ void __launch_bounds__(256)
edge_fused(const float* __restrict__ edge, const int* __restrict__ src,
           const int* __restrict__ dst, int E,
           const float* __restrict__ A0_b, const float* __restrict__ A1_b,
           const float* __restrict__ A2_b, const float* __restrict__ Em0_b,
           const float* __restrict__ Em1_b, const float* __restrict__ Em2_b,
           const float* __restrict__ attn, float* __restrict__ out_edge)
{
    extern __shared__ float sm[];
    float* sX  = sm;            // 64*260
    float* sY  = sm + 16640;    // 64*260
    float* sW  = sm + 33280;    // 2*256*20
    float* sSc = sm + 43520;    // 64*4
    int*   sS  = (int*)(sm + 43776);
    int*   sD  = (int*)(sm + 43840);
    const unsigned sWu = smem_u32(sW);

    const int tid = threadIdx.x;
    const int e0 = blockIdx.x * 64;
    const int lane = tid & 31, wid = tid >> 5;
    const int wm = wid & 1, wn = wid >> 1;
    const int lq = lane >> 2, lc = lane & 3;

    if (tid < 64) {
        int e = min(e0 + tid, E - 1);
        sS[tid] = src[e]; sD[tid] = dst[e];
    }
    // edge tile [64,128] -> sY (tf32)
    for (int i = tid; i < 64 * 32; i += 256) {
        int r = i >> 5, q = i & 31;
        float4 v = make_float4(0.f, 0.f, 0.f, 0.f);
        if (e0 + r < E) v = *(const float4*)(edge + (size_t)(e0 + r) * 128 + q * 4);
        v.x = to_tf32(v.x); v.y = to_tf32(v.y); v.z = to_tf32(v.z); v.w = to_tf32(v.w);
        *(float4*)(sY + r * 260 + q * 4) = v;
    }
    __syncthreads();

    // ---- stage 0: sX = relu(edge@Wcomb + Pi[dst] + Pj[src] + A0_b) ----
    {
        float acc[2][8][4];
        gemm_stage<8>(sY, g_BtComb, 128, sW, sWu, tid, acc);
#pragma unroll
        for (int mf = 0; mf < 2; mf++)
#pragma unroll
            for (int nf = 0; nf < 8; nf++) {
                int col = wn * 64 + nf * 8 + lc * 2;
                float2 bb = *(const float2*)(A0_b + col);
#pragma unroll
                for (int h = 0; h < 2; h++) {
                    int r = wm * 32 + mf * 16 + h * 8 + lq;
                    int d = sD[r], s = sS[r];
                    float2 pi = *(const float2*)(g_Pi + (size_t)d * 256 + col);
                    float2 pj = *(const float2*)(g_Pj + (size_t)s * 256 + col);
                    sX[r * 260 + col]     = to_tf32(fmaxf(acc[mf][nf][h*2+0] + pi.x + pj.x + bb.x, 0.f));
                    sX[r * 260 + col + 1] = to_tf32(fmaxf(acc[mf][nf][h*2+1] + pi.y + pj.y + bb.y, 0.f));
                }
            }
    }
    __syncthreads();

    // ---- stage 1: sY = relu(sX@A1 + b1) ----
    {
        float acc[2][8][4];
        gemm_stage<8>(sX, g_BtA1, 256, sW, sWu, tid, acc);
#pragma unroll
        for (int mf = 0; mf < 2; mf++)
#pragma unroll
            for (int nf = 0; nf < 8; nf++) {
                int col = wn * 64 + nf * 8 + lc * 2;
                float2 bb = *(const float2*)(A1_b + col);
#pragma unroll
                for (int h = 0; h < 2; h++) {
                    int r = wm * 32 + mf * 16 + h * 8 + lq;
                    sY[r * 260 + col]     = to_tf32(fmaxf(acc[mf][nf][h*2+0] + bb.x, 0.f));
                    sY[r * 260 + col + 1] = to_tf32(fmaxf(acc[mf][nf][h*2+1] + bb.y, 0.f));
                }
            }
    }
    __syncthreads();

    // ---- stage 2: sX = relu(sY@A2 + b2), fused attention scores ----
    {
        float acc[2][8][4];
        gemm_stage<8>(sY, g_BtA2, 256, sW, sWu, tid, acc);
        float sp[2][2] = {{0.f, 0.f}, {0.f, 0.f}};
#pragma unroll
        for (int mf = 0; mf < 2; mf++)
#pragma unroll
            for (int nf = 0; nf < 8; nf++) {
                int col = wn * 64 + nf * 8 + lc * 2;
                float2 bb = *(const float2*)(A2_b + col);
                float2 av = *(const float2*)(attn + col);
#pragma unroll
                for (int h = 0; h < 2; h++) {
                    int r = wm * 32 + mf * 16 + h * 8 + lq;
                    float v0 = fmaxf(acc[mf][nf][h*2+0] + bb.x, 0.f);
                    float v1 = fmaxf(acc[mf][nf][h*2+1] + bb.y, 0.f);
                    sX[r * 260 + col]     = to_tf32(v0);
                    sX[r * 260 + col + 1] = to_tf32(v1);
                    sp[mf][h] += v0 * av.x + v1 * av.y;
                }
            }
        // reduce across the 4 lanes of each row-quad (lc = 0..3)
#pragma unroll
        for (int mf = 0; mf < 2; mf++)
#pragma unroll
            for (int h = 0; h < 2; h++) {
                float v = sp[mf][h];
                v += __shfl_xor_sync(0xffffffffu, v, 1);
                v += __shfl_xor_sync(0xffffffffu, v, 2);
                if (lc == 0) sSc[(wm * 32 + mf * 16 + h * 8 + lq) * 4 + wn] = v;
            }
    }
    __syncthreads();

    // ---- stage 3: sY(cols 0..63) = relu(sX@Em0 + b) ----
    {
        float acc[2][2][4];
        gemm_stage<2>(sX, g_BtEm0, 256, sW, sWu, tid, acc);
#pragma unroll
        for (int mf = 0; mf < 2; mf++)
#pragma unroll
            for (int nf = 0; nf < 2; nf++) {
                int col = wn * 16 + nf * 8 + lc * 2;
                float2 bb = *(const float2*)(Em0_b + col);
#pragma unroll
                for (int h = 0; h < 2; h++) {
                    int r = wm * 32 + mf * 16 + h * 8 + lq;
                    sY[r * 260 + col]     = to_tf32(fmaxf(acc[mf][nf][h*2+0] + bb.x, 0.f));
                    sY[r * 260 + col + 1] = to_tf32(fmaxf(acc[mf][nf][h*2+1] + bb.y, 0.f));
                }
            }
    }
    __syncthreads();

    // ---- stage 4: sX(cols 0..63) = relu(sY@Em1 + b) ----
    {
        float acc[2][2][4];
        gemm_stage<2>(sY, g_BtEm1, 64, sW, sWu, tid, acc);
#pragma unroll
        for (int mf = 0; mf < 2; mf++)
#pragma unroll
            for (int nf = 0; nf < 2; nf++) {
                int col = wn * 16 + nf * 8 + lc * 2;
                float2 bb = *(const float2*)(Em1_b + col);
#pragma unroll
                for (int h = 0; h < 2; h++) {
                    int r = wm * 32 + mf * 16 + h * 8 + lq;
                    sX[r * 260 + col]     = to_tf32(fmaxf(acc[mf][nf][h*2+0] + bb.x, 0.f));
                    sX[r * 260 + col + 1] = to_tf32(fmaxf(acc[mf][nf][h*2+1] + bb.y, 0.f));
                }
            }
    }
    __syncthreads();

    // ---- stage 5: out_edge = relu(sX@Em2 + b) + Et ----
    {
        float acc[2][2][4];
        gemm_stage<2>(sX, g_BtEm2, 64, sW, sWu, tid, acc);
#pragma unroll
        for (int mf = 0; mf < 2; mf++)
#pragma unroll
            for (int nf = 0; nf < 2; nf++) {
                int col = wn * 16 + nf * 8 + lc * 2;
                float2 bb = *(const float2*)(Em2_b + col);
#pragma unroll
                for (int h = 0; h < 2; h++) {
                    int r = wm * 32 + mf * 16 + h * 8 + lq;
                    if (e0 + r < E) {
                        float2 et = *(const float2*)(g_Et + (size_t)(e0 + r) * 64 + col);
                        float2 o;
                        o.x = fmaxf(acc[mf][nf][h*2+0] + bb.x, 0.f) + et.x;
                        o.y = fmaxf(acc[mf][nf][h*2+1] + bb.y, 0.f) + et.y;
                        *(float2*)(out_edge + (size_t)(e0 + r) * 64 + col) = o;
                    }
                }
            }
    }
    __syncthreads();

    // ---- write scores + segment max ----
    {
        int r = tid >> 2, h = tid & 3;
        if (e0 + r < E) {
            float v = sSc[tid];
            g_scores[(size_t)(e0 + r) * 4 + h] = v;
            atomicMaxFloat(&g_smax[(size_t)sD[r] * 4 + h], v);
        }
    }
}

// ---------------- tf32 warp-MMA GEMM (node-level) ----------------
template<int BN, bool BIASRELU>
__global__ void __launch_bounds__(256)
mma_gemm(const float* __restrict__ A, const float* __restrict__ Bt,
         const float* __restrict__ bias, float* __restrict__ C,
         int M, int K, int ldc)
{
    constexpr int NF = BN / 16;
    constexpr int WN = BN / 2;
    __shared__ float As[128][20];
    __shared__ float Bs[BN][20];

    const int tid = threadIdx.x;
    const int lane = tid & 31, wid = tid >> 5;
    const int wm = wid & 3, wn = wid >> 2;
    const int m0 = blockIdx.x * 128;
    const int n0 = blockIdx.y * BN;
    const int lq = lane >> 2;
    const int lc = lane & 3;

    float acc[2][NF][4];
#pragma unroll
    for (int i = 0; i < 2; i++)
#pragma unroll
        for (int j = 0; j < NF; j++)
#pragma unroll
            for (int q = 0; q < 4; q++) acc[i][j][q] = 0.0f;

    for (int k0 = 0; k0 < K; k0 += 16) {
#pragma unroll
        for (int i = tid; i < 512; i += 256) {
            int m = i >> 2, q = i & 3;
            float4 v = make_float4(0.f, 0.f, 0.f, 0.f);
            int row = m0 + m;
            if (row < M) v = *reinterpret_cast<const float4*>(A + (size_t)row * K + k0 + q * 4);
            v.x = to_tf32(v.x); v.y = to_tf32(v.y); v.z = to_tf32(v.z); v.w = to_tf32(v.w);
            *reinterpret_cast<float4*>(&As[m][q * 4]) = v;
        }
#pragma unroll
        for (int i = tid; i < BN * 4; i += 256) {
            int n = i >> 2, q = i & 3;
            float4 v = *reinterpret_cast<const float4*>(Bt + (size_t)(n0 + n) * K + k0 + q * 4);
            *reinterpret_cast<float4*>(&Bs[n][q * 4]) = v;
        }
        __syncthreads();

#pragma unroll
        for (int kk = 0; kk < 16; kk += 8) {
            unsigned a[2][4];
#pragma unroll
            for (int mf = 0; mf < 2; mf++) {
                int m = wm * 32 + mf * 16 + lq;
                a[mf][0] = __float_as_uint(As[m][kk + lc]);
                a[mf][1] = __float_as_uint(As[m + 8][kk + lc]);
                a[mf][2] = __float_as_uint(As[m][kk + 4 + lc]);
                a[mf][3] = __float_as_uint(As[m + 8][kk + 4 + lc]);
            }
            unsigned b[NF][2];
#pragma unroll
            for (int nf = 0; nf < NF; nf++) {
                int n = wn * WN + nf * 8 + lq;
                b[nf][0] = __float_as_uint(Bs[n][kk + lc]);
                b[nf][1] = __float_as_uint(Bs[n][kk + 4 + lc]);
            }
#pragma unroll
            for (int mf = 0; mf < 2; mf++)
#pragma unroll
                for (int nf = 0; nf < NF; nf++)
                    mma_tf32(acc[mf][nf], a[mf], b[nf]);
        }
        __syncthreads();
    }

#pragma unroll
    for (int mf = 0; mf < 2; mf++) {
#pragma unroll
        for (int nf = 0; nf < NF; nf++) {
            int row = m0 + wm * 32 + mf * 16 + lq;
            int col = n0 + wn * WN + nf * 8 + lc * 2;
            float2 bv = make_float2(0.f, 0.f);
            if (BIASRELU) bv = *reinterpret_cast<const float2*>(bias + col);
            float2 v0 = make_float2(acc[mf][nf][0], acc[mf][nf][1]);
            float2 v1 = make_float2(acc[mf][nf][2], acc[mf][nf][3]);
            if (BIASRELU) {
                v0.x = fmaxf(v0.x + bv.x, 0.f); v0.y = fmaxf(v0.y + bv.y, 0.f);
                v1.x = fmaxf(v1.x + bv.x, 0.f); v1.y = fmaxf(v1.y + bv.y, 0.f);
            }
            if (row < M)
                *reinterpret_cast<float2*>(C + (size_t)row * ldc + col) = v0;
            if (row + 8 < M)
                *reinterpret_cast<float2*>(C + (size_t)(row + 8) * ldc + col) = v1;
        }
    }
}

// transpose W[K,N] -> Bt[N,K], rounded to tf32
__global__ void transpose_tf32(const float* __restrict__ W, float* __restrict__ Bt, int K, int Nd)
{
    int i = blockIdx.x * blockDim.x + threadIdx.x;
    if (i >= K * Nd) return;
    int n = i / K, k = i % K;
    Bt[i] = to_tf32(W[(size_t)k * Nd + n]);
}

// ---------------- generic tiled fp32 SGEMM ----------------
template<int BM, int BN, int BK, int TM, int TN, bool RELU, bool BIAS, bool RES>
__global__ void __launch_bounds__((BM / TM) * (BN / TN))
sgemm(const float* __restrict__ A, int lda,
      const float* __restrict__ W,
      const float* __restrict__ bias,
      const float* __restrict__ res, int ldres,
      float* __restrict__ C, int ldc,
      int M, int N, int K)
{
    constexpr int NT = (BM / TM) * (BN / TN);
    __shared__ float As[BK][BM + 4];
    __shared__ float Ws[BK][BN];

    const int tid = threadIdx.x;
    const int tx = tid % (BN / TN);
    const int ty = tid / (BN / TN);
    const int m0 = blockIdx.x * BM;
    const int n0 = blockIdx.y * BN;

    float acc[TM][TN];
#pragma unroll
    for (int i = 0; i < TM; i++)
#pragma unroll
        for (int j = 0; j < TN; j++) acc[i][j] = 0.0f;

    for (int k0 = 0; k0 < K; k0 += BK) {
#pragma unroll
        for (int i = tid; i < BM * BK / 4; i += NT) {
            int m  = i / (BK / 4);
            int k4 = i % (BK / 4);
            float4 v = make_float4(0.f, 0.f, 0.f, 0.f);
            int row = m0 + m;
            if (row < M)
                v = *reinterpret_cast<const float4*>(A + (size_t)row * lda + k0 + k4 * 4);
            As[k4 * 4 + 0][m] = v.x;
            As[k4 * 4 + 1][m] = v.y;
            As[k4 * 4 + 2][m] = v.z;
            As[k4 * 4 + 3][m] = v.w;
        }
#pragma unroll
        for (int i = tid; i < BK * BN / 4; i += NT) {
            int k  = i / (BN / 4);
            int n4 = i % (BN / 4);
            *reinterpret_cast<float4*>(&Ws[k][n4 * 4]) =
                *reinterpret_cast<const float4*>(W + (size_t)(k0 + k) * N + n0 + n4 * 4);
        }
        __syncthreads();

#pragma unroll
        for (int k = 0; k < BK; k++) {
            float a[TM], b[TN];
#pragma unroll
            for (int i = 0; i < TM; i++) a[i] = As[k][ty * TM + i];
#pragma unroll
            for (int j = 0; j < TN; j++) b[j] = Ws[k][tx * TN + j];
#pragma unroll
            for (int i = 0; i < TM; i++)
#pragma unroll
                for (int j = 0; j < TN; j++)
                    acc[i][j] = fmaf(a[i], b[j], acc[i][j]);
        }
        __syncthreads();
    }

#pragma unroll
    for (int i = 0; i < TM; i++) {
        int row = m0 + ty * TM + i;
        if (row >= M) continue;
#pragma unroll
        for (int j = 0; j < TN; j++) {
            int col = n0 + tx * TN + j;
            float v = acc[i][j];
            if (BIAS) v += bias[col];
            if (RELU) v = fmaxf(v, 0.0f);
            if (RES)  v += res[(size_t)row * ldres + col];
            C[(size_t)row * ldc + col] = v;
        }
    }
}

// ---------------- small helper kernels ----------------
__global__ void init_kernel(int N)
{
    int i = blockIdx.x * blockDim.x + threadIdx.x;
    if (i < N * 4) { g_smax[i] = -INFINITY; g_den[i] = 0.0f; }
    if (i < N * 256) g_agg[i] = 0.0f;
    if (i < N) g_deg[i] = 1.0f;
}

__global__ void ex_kernel(const int* __restrict__ dst, int E)
{
    int i = blockIdx.x * blockDim.x + threadIdx.x;
    if (i >= E * 4) return;
    int e = i >> 2, h = i & 3;
    int d = dst[e];
    float v = expf(g_scores[i] - g_smax[d * 4 + h]);
    g_ex[i] = v;
    atomicAdd(&g_den[d * 4 + h], v);
}

__global__ void agg_kernel(const int* __restrict__ src, const int* __restrict__ dst, int E,
                           const float* __restrict__ linW, float* __restrict__ attn_out)
{
    int idx = blockIdx.x * blockDim.x + threadIdx.x;
    int e = idx >> 6;
    int t = idx & 63;
    if (e >= E) return;
    int d = dst[e], s = src[e];
    int h = t >> 4;
    float alpha = g_ex[e * 4 + h] / g_den[(size_t)d * 4 + h];
    if (t == 0) {
        float aw = 0.0f;
#pragma unroll
        for (int hh = 0; hh < 4; hh++)
            aw += (g_ex[e * 4 + hh] / g_den[(size_t)d * 4 + hh]) * linW[hh];
        attn_out[e] = aw;
    }
    float4 xj = reinterpret_cast<const float4*>(g_Xni + (size_t)s * 256)[t];
    float4 m = make_float4(xj.x * alpha, xj.y * alpha, xj.z * alpha, xj.w * alpha);
    atomicAdd4(reinterpret_cast<float4*>(g_agg + (size_t)d * 256 + t * 4), m);
}

__global__ void deg_kernel(const int* __restrict__ src, const int* __restrict__ dst, int E)
{
    int e = blockIdx.x * blockDim.x + threadIdx.x;
    if (e >= E) return;
    int s = src[e];
    if (s != dst[e]) atomicAdd(&g_deg[s], 1.0f);
}

__global__ void dinv_kernel(int N)
{
    int n = blockIdx.x * blockDim.x + threadIdx.x;
    if (n < N) g_dinv[n] = rsqrtf(g_deg[n]);
}

__global__ void outinit_kernel(const float* __restrict__ gcn_b, float* __restrict__ out, int N)
{
    int i = blockIdx.x * blockDim.x + threadIdx.x;
    if (i >= N * 64) return;
    int n = i >> 6;
    float di = g_dinv[n];
    out[i] = gcn_b[i & 63] + di * di * g_xg[i];
}

__global__ void gcn_scatter_kernel(const int* __restrict__ src, const int* __restrict__ dst,
                                   int E, float* __restrict__ out)
{
    int idx = blockIdx.x * blockDim.x + threadIdx.x;
    int e = idx >> 4;
    int t = idx & 15;
    if (e >= E) return;
    int s = src[e], d = dst[e];
    if (s == d) return;
    float w = g_dinv[s] * g_dinv[d];
    float4 v = reinterpret_cast<const float4*>(g_xg + (size_t)s * 64)[t];
    float4 m = make_float4(v.x * w, v.y * w, v.z * w, v.w * w);
    atomicAdd4(reinterpret_cast<float4*>(out + (size_t)d * 64 + t * 4), m);
}

// ---------------- launch ----------------
extern "C" void kernel_launch(void* const* d_in, const int* in_sizes, int n_in,
                              void* d_out, int out_size)
{
    const float* node = (const float*)d_in[0];
    const float* edge = (const float*)d_in[1];
    const int*   ei   = (const int*)d_in[2];
    const float* W_ni = (const float*)d_in[3];
    const float* W_nj = (const float*)d_in[4];
    const float* W_eij= (const float*)d_in[5];
    const float* W_nt = (const float*)d_in[6];
    const float* b_nt = (const float*)d_in[7];
    const float* W_et = (const float*)d_in[8];
    const float* b_et = (const float*)d_in[9];
    const float* A0_W = (const float*)d_in[10];
    const float* A0_b = (const float*)d_in[11];
    const float* A1_W = (const float*)d_in[12];
    const float* A1_b = (const float*)d_in[13];
    const float* A2_W = (const float*)d_in[14];
    const float* A2_b = (const float*)d_in[15];
    const float* attn = (const float*)d_in[16];
    const float* Nm0_W= (const float*)d_in[17];
    const float* Nm0_b= (const float*)d_in[18];
    const float* Nm1_W= (const float*)d_in[19];
    const float* Nm1_b= (const float*)d_in[20];
    const float* Nm2_W= (const float*)d_in[21];
    const float* Nm2_b= (const float*)d_in[22];
    const float* Em0_W= (const float*)d_in[23];
    const float* Em0_b= (const float*)d_in[24];
    const float* Em1_W= (const float*)d_in[25];
    const float* Em1_b= (const float*)d_in[26];
    const float* Em2_W= (const float*)d_in[27];
    const float* Em2_b= (const float*)d_in[28];
    const float* linW = (const float*)d_in[29];
    const float* gcnW = (const float*)d_in[30];
    const float* gcnb = (const float*)d_in[31];

    const int N = in_sizes[0] / 256;
    const int E = in_sizes[2] / 2;
    const int* src = ei;
    const int* dst = ei + E;

    float* out      = (float*)d_out;
    float* out_node = out;
    float* out_edge = out + (size_t)N * 64;
    float* out_attn = out_edge + (size_t)E * 64;

    void* p;
    cudaGetSymbolAddress(&p, g_Xni);   float* pXni = (float*)p;
    cudaGetSymbolAddress(&p, g_Xnt);   float* pXnt = (float*)p;
    cudaGetSymbolAddress(&p, g_Et);    float* pEt  = (float*)p;
    cudaGetSymbolAddress(&p, g_Pi);    float* pPi  = (float*)p;
    cudaGetSymbolAddress(&p, g_Pj);    float* pPj  = (float*)p;
    cudaGetSymbolAddress(&p, g_Wcomb); float* pWcomb = (float*)p;
    cudaGetSymbolAddress(&p, g_Wfold); float* pWfold = (float*)p;
    cudaGetSymbolAddress(&p, g_agg);   float* pAgg = (float*)p;
    cudaGetSymbolAddress(&p, g_NM0);   float* pNM0 = (float*)p;
    cudaGetSymbolAddress(&p, g_NM1);   float* pNM1 = (float*)p;
    cudaGetSymbolAddress(&p, g_nodeout); float* pNodeOut = (float*)p;
    cudaGetSymbolAddress(&p, g_xg);    float* pXg  = (float*)p;
    cudaGetSymbolAddress(&p, g_BtA1);   float* pBtA1 = (float*)p;
    cudaGetSymbolAddress(&p, g_BtA2);   float* pBtA2 = (float*)p;
    cudaGetSymbolAddress(&p, g_BtComb); float* pBtComb = (float*)p;
    cudaGetSymbolAddress(&p, g_BtEm0);  float* pBtEm0 = (float*)p;
    cudaGetSymbolAddress(&p, g_BtEm1);  float* pBtEm1 = (float*)p;
    cudaGetSymbolAddress(&p, g_BtEm2);  float* pBtEm2 = (float*)p;
    cudaGetSymbolAddress(&p, g_BtNi);   float* pBtNi = (float*)p;
    cudaGetSymbolAddress(&p, g_BtFold); float* pBtFold = (float*)p;
    cudaGetSymbolAddress(&p, g_BtPj);   float* pBtPj = (float*)p;

    const int TPB = 256;
    const int MT_N = (N + 127) / 128;
    const int ET = (E + 63) / 64;                 // fused edge tiles
    const int FUSED_SMEM = 43904 * 4;             // 171.5 KB
    cudaFuncSetAttribute(edge_fused, cudaFuncAttributeMaxDynamicSharedMemorySize, FUSED_SMEM);

    // 1. init reductions
    init_kernel<<<(N * 256 + TPB - 1) / TPB, TPB>>>(N);

    // 2a. weight folds (fp32)
    {
        dim3 g(2, 2);
        sgemm<128,128,16,8,8,false,false,false><<<g, 256>>>(W_nj, 256, A0_W, nullptr, nullptr, 0, pWfold, 256, 256, 256, 256);
    }
    {
        dim3 g(1, 2);
        sgemm<128,128,16,8,8,false,false,false><<<g, 256>>>(W_eij, 256, A0_W + 256 * 256, nullptr, nullptr, 0, pWcomb, 256, 128, 256, 256);
    }

    // 2b. transposed tf32 weights
    transpose_tf32<<<256, 256>>>(A1_W, pBtA1, 256, 256);
    transpose_tf32<<<256, 256>>>(A2_W, pBtA2, 256, 256);
    transpose_tf32<<<128, 256>>>(pWcomb, pBtComb, 128, 256);
    transpose_tf32<<<64, 256>>>(Em0_W, pBtEm0, 256, 64);
    transpose_tf32<<<16, 256>>>(Em1_W, pBtEm1, 64, 64);
    transpose_tf32<<<16, 256>>>(Em2_W, pBtEm2, 64, 64);
    transpose_tf32<<<256, 256>>>(W_ni, pBtNi, 256, 256);
    transpose_tf32<<<256, 256>>>(pWfold, pBtFold, 256, 256);
    transpose_tf32<<<256, 256>>>(A0_W + 512 * 256, pBtPj, 256, 256);

    // 2c. node-level projections
    {
        dim3 g(MT_N, 2);
        mma_gemm<128, false><<<g, 256>>>(node, pBtNi,   nullptr, pXni, N, 256, 256);
        mma_gemm<128, false><<<g, 256>>>(node, pBtFold, nullptr, pPi,  N, 256, 256);
        mma_gemm<128, false><<<g, 256>>>(pXni, pBtPj,   nullptr, pPj,  N, 256, 256);
    }
    {
        dim3 g(MT_N, 1);
        sgemm<128,64,16,8,4,false,true,false><<<g, 256>>>(node, 256, W_nt, b_nt, nullptr, 0, pXnt, 64, N, 64, 256);
    }

    // 2d. Et (fp32; feeds fused-kernel residual)
    {
        dim3 g((E + 127) / 128, 1);
        sgemm<128,64,16,8,4,false,true,false><<<g, 256>>>(edge, 128, W_et, b_et, nullptr, 0, pEt, 64, E, 64, 128);
    }

    // 3. fused edge chain: comb+gather+relu -> A1 -> A2(+scores) -> Em0..Em2 -> out_edge
    edge_fused<<<ET, 256, FUSED_SMEM>>>(edge, src, dst, E, A0_b, A1_b, A2_b,
                                        Em0_b, Em1_b, Em2_b, attn, out_edge);

    // 4. softmax denominators + message aggregation
    ex_kernel<<<((size_t)E * 4 + TPB - 1) / TPB, TPB>>>(dst, E);
    agg_kernel<<<((size_t)E * 64 + TPB - 1) / TPB, TPB>>>(src, dst, E, linW, out_attn);

    // 5. node MLP (+ residual node@W_nt + b_nt)
    {
        dim3 g(MT_N, 1);
        sgemm<128,64,16,8,4,true,true,false><<<g, 256>>>(pAgg, 256, Nm0_W, Nm0_b, nullptr, 0, pNM0, 64, N, 64, 256);
        sgemm<128,64,16,8,4,true,true,false><<<g, 256>>>(pNM0, 64, Nm1_W, Nm1_b, nullptr, 0, pNM1, 64, N, 64, 64);
        sgemm<128,64,16,8,4,true,true,true><<<g, 256>>>(pNM1, 64, Nm2_W, Nm2_b, pXnt, 64, pNodeOut, 64, N, 64, 64);
    }

    // 6. GCN
    deg_kernel<<<(E + TPB - 1) / TPB, TPB>>>(src, dst, E);
    dinv_kernel<<<(N + TPB - 1) / TPB, TPB>>>(N);
    {
        dim3 g(MT_N, 1);
        sgemm<128,64,16,8,4,false,false,false><<<g, 256>>>(pNodeOut, 64, gcnW, nullptr, nullptr, 0, pXg, 64, N, 64, 64);
    }
    outinit_kernel<<<(N * 64 + TPB - 1) / TPB, TPB>>>(gcnb, out_node, N);
    gcn_scatter_kernel<<<((size_t)E * 16 + TPB - 1) / TPB, TPB>>>(src, dst, E, out_node);
}

// round 8
// speedup vs baseline: 3.2375x; 1.1539x over previous
#include <cuda_runtime.h>
#include <math.h>

// ---------------- problem constants ----------------
#define MAXN 10000
#define MAXE 160000
// HC = 256, C = 64, H = 4

// ---------------- scratch (device globals; no allocation) ----------------
__device__ float g_Xni[MAXN * 256];
__device__ float g_Xnt[MAXN * 64];
__device__ float g_Pi [MAXN * 256];
__device__ float g_Pj [MAXN * 256];
__device__ float g_Wcomb[128 * 256];
__device__ float g_Wfold[256 * 256];
__device__ float g_scores[MAXE * 4];
__device__ float g_ex  [MAXE * 4];
__device__ float g_smax[MAXN * 4];
__device__ float g_den [MAXN * 4];
__device__ float g_agg [MAXN * 256];
__device__ float g_NM0 [MAXN * 64];
__device__ float g_NM1 [MAXN * 64];
__device__ float g_nodeout[MAXN * 64];
__device__ float g_deg [MAXN];
__device__ float g_dinv[MAXN];
__device__ float g_xg  [MAXN * 64];
// transposed tf32 weights [N,K] (K contiguous)
__device__ float g_BtA1  [256 * 256];
__device__ float g_BtA2  [256 * 256];
__device__ float g_BtComb[256 * 128];
__device__ float g_BtEm0 [64 * 256];
__device__ float g_BtEm1 [64 * 64];
__device__ float g_BtEm2 [64 * 64];
__device__ float g_BtEt  [64 * 128];
__device__ float g_BtNi  [256 * 256];
__device__ float g_BtFold[256 * 256];
__device__ float g_BtPj  [256 * 256];

static __device__ __forceinline__ float to_tf32(float x) {
    float r; asm("cvt.rna.tf32.f32 %0, %1;" : "=f"(r) : "f"(x)); return r;
}
static __device__ __forceinline__ void mma_tf32(float* d, const unsigned* a, const unsigned* b) {
    asm volatile(
        "mma.sync.aligned.m16n8k8.row.col.f32.tf32.tf32.f32 "
        "{%0,%1,%2,%3}, {%4,%5,%6,%7}, {%8,%9}, {%0,%1,%2,%3};"
        : "+f"(d[0]), "+f"(d[1]), "+f"(d[2]), "+f"(d[3])
        : "r"(a[0]), "r"(a[1]), "r"(a[2]), "r"(a[3]), "r"(b[0]), "r"(b[1]));
}
static __device__ __forceinline__ unsigned smem_u32(const void* p) {
    unsigned a;
    asm("{ .reg .u64 t; cvta.to.shared.u64 t, %1; cvt.u32.u64 %0, t; }" : "=r"(a) : "l"(p));
    return a;
}
static __device__ __forceinline__ void cpa16(unsigned dst, const float* src) {
    asm volatile("cp.async.ca.shared.global [%0], [%1], 16;" :: "r"(dst), "l"(src));
}
static __device__ __forceinline__ void atomicAdd4(float4* a, float4 v) {
#if !defined(__CUDA_ARCH__) || __CUDA_ARCH__ >= 900
    atomicAdd(a, v);
#else
    atomicAdd(&a->x, v.x); atomicAdd(&a->y, v.y);
    atomicAdd(&a->z, v.z); atomicAdd(&a->w, v.w);
#endif
}
__device__ __forceinline__ void atomicMaxFloat(float* addr, float v)
{
    if (v >= 0.0f) atomicMax(reinterpret_cast<int*>(addr), __float_as_int(v));
    else           atomicMin(reinterpret_cast<unsigned int*>(addr), __float_as_uint(v));
}

// ---------------- fused edge-chain building block ----------------
// acc[2][NF][4] = sA[128,K](stride 260) @ Bt[NF*16,K]^T  for this warp.
// Weights streamed global->smem via cp.async, double-buffered 16-wide K chunks.
// 8 warps: wm = wid&3 (4 x 32 rows), wn = wid>>2 (2 n-strips of NF*8 cols).
template<int NF>
static __device__ __forceinline__ void gemm_stage(
    const float* __restrict__ sA, const float* __restrict__ Bt, int K,
    float* __restrict__ sW, unsigned sWu, int tid, float (&acc)[2][NF][4])
{
    constexpr int NTOT = NF * 16;
    const int lane = tid & 31, wid = tid >> 5;
    const int wm = wid & 3, wn = wid >> 2;
    const int lq = lane >> 2, lc = lane & 3;
    const int NC = K >> 4;

#pragma unroll
    for (int i = 0; i < 2; i++)
#pragma unroll
        for (int j = 0; j < NF; j++)
#pragma unroll
            for (int q = 0; q < 4; q++) acc[i][j][q] = 0.f;

    // preload chunk 0 into buf 0
    for (int i = tid; i < NTOT * 4; i += 256) {
        int n = i >> 2, q = i & 3;
        cpa16(sWu + (unsigned)(n * 20 + q * 4) * 4u, Bt + (size_t)n * K + q * 4);
    }
    asm volatile("cp.async.commit_group;");

    for (int c = 0; c < NC; c++) {
        if (c + 1 < NC) {
            unsigned boff = (unsigned)(((c + 1) & 1) * NTOT * 20) * 4u;
            for (int i = tid; i < NTOT * 4; i += 256) {
                int n = i >> 2, q = i & 3;
                cpa16(sWu + boff + (unsigned)(n * 20 + q * 4) * 4u,
                      Bt + (size_t)n * K + (c + 1) * 16 + q * 4);
            }
            asm volatile("cp.async.commit_group;");
            asm volatile("cp.async.wait_group 1;");
        } else {
            asm volatile("cp.async.wait_group 0;");
        }
        __syncthreads();
        const float* B = sW + (c & 1) * NTOT * 20;
        const int kb = c * 16;
#pragma unroll
        for (int kk = 0; kk < 16; kk += 8) {
            unsigned a[2][4];
#pragma unroll
            for (int mf = 0; mf < 2; mf++) {
                int m = wm * 32 + mf * 16 + lq;
                a[mf][0] = __float_as_uint(sA[m * 260 + kb + kk + lc]);
                a[mf][1] = __float_as_uint(sA[(m + 8) * 260 + kb + kk + lc]);
                a[mf][2] = __float_as_uint(sA[m * 260 + kb + kk + 4 + lc]);
                a[mf][3] = __float_as_uint(sA[(m + 8) * 260 + kb + kk + 4 + lc]);
            }
#pragma unroll
            for (int nf = 0; nf < NF; nf++) {
                unsigned b[2];
                int n = wn * (NF * 8) + nf * 8 + lq;
                b[0] = __float_as_uint(B[n * 20 + kk + lc]);
                b[1] = __float_as_uint(B[n * 20 + kk + 4 + lc]);
#pragma unroll
                for (int mf = 0; mf < 2; mf++)
                    mma_tf32(acc[mf][nf], a[mf], b);
            }
        }
        __syncthreads();
    }
}

// ---------------- fused edge mega-kernel (128-edge tiles, in-place) ----------------
// Per tile: Et(comb residual) ; comb+gather+relu -> A1 -> A2(+scores) -> Em0 ->
// Em1 -> Em2(+Et -> out_edge). Single activation buffer, outputs in registers.
__global__ void __launch_bounds__(256)
edge_fused(const float* __restrict__ edge, const int* __restrict__ src,
           const int* __restrict__ dst, int E,
           const float* __restrict__ A0_b, const float* __restrict__ A1_b,
           const float* __restrict__ A2_b, const float* __restrict__ Em0_b,
           const float* __restrict__ Em1_b, const float* __restrict__ Em2_b,
           const float* __restrict__ b_et,
           const float* __restrict__ attn, float* __restrict__ out_edge)
{
    extern __shared__ float sm[];
    float* sA  = sm;             // 128*260 = 33280
    float* sW  = sm + 33280;     // 2*256*20 = 10240
    float* sEt = sm + 43520;     // 128*66 = 8448
    float* sSc = sm + 51968;     // 128*4 = 512
    int*   sS  = (int*)(sm + 52480);   // 128
    int*   sD  = (int*)(sm + 52608);   // 128
    const unsigned sWu = smem_u32(sW);

    const int tid = threadIdx.x;
    const int e0 = blockIdx.x * 128;
    const int lane = tid & 31, wid = tid >> 5;
    const int wm = wid & 3, wn = wid >> 2;
    const int lq = lane >> 2, lc = lane & 3;

    if (tid < 128) {
        int e = min(e0 + tid, E - 1);
        sS[tid] = src[e]; sD[tid] = dst[e];
    }
    // edge tile [128,128] -> sA cols 0..127 (tf32)
    for (int i = tid; i < 128 * 32; i += 256) {
        int r = i >> 5, q = i & 31;
        float4 v = make_float4(0.f, 0.f, 0.f, 0.f);
        if (e0 + r < E) v = *(const float4*)(edge + (size_t)(e0 + r) * 128 + q * 4);
        v.x = to_tf32(v.x); v.y = to_tf32(v.y); v.z = to_tf32(v.z); v.w = to_tf32(v.w);
        *(float4*)(sA + r * 260 + q * 4) = v;
    }
    __syncthreads();

    // ---- stage Et: sEt = edge@W_et + b_et (no relu) ----
    {
        float acc[2][4][4];
        gemm_stage<4>(sA, g_BtEt, 128, sW, sWu, tid, acc);
#pragma unroll
        for (int mf = 0; mf < 2; mf++)
#pragma unroll
            for (int nf = 0; nf < 4; nf++) {
                int col = wn * 32 + nf * 8 + lc * 2;
                float2 bb = *(const float2*)(b_et + col);
#pragma unroll
                for (int h = 0; h < 2; h++) {
                    int r = wm * 32 + mf * 16 + h * 8 + lq;
                    sEt[r * 66 + col]     = acc[mf][nf][h*2+0] + bb.x;
                    sEt[r * 66 + col + 1] = acc[mf][nf][h*2+1] + bb.y;
                }
            }
    }
    // (no sync needed: sEt untouched until stage 5; sW reuse guarded inside gemm_stage)

    // ---- stage 0: sA = relu(edge@Wcomb + Pi[dst] + Pj[src] + A0_b)  (in place) ----
    {
        float acc[2][16][4];
        gemm_stage<16>(sA, g_BtComb, 128, sW, sWu, tid, acc);
#pragma unroll
        for (int mf = 0; mf < 2; mf++)
#pragma unroll
            for (int nf = 0; nf < 16; nf++) {
                int col = wn * 128 + nf * 8 + lc * 2;
                float2 bb = *(const float2*)(A0_b + col);
#pragma unroll
                for (int h = 0; h < 2; h++) {
                    int r = wm * 32 + mf * 16 + h * 8 + lq;
                    int d = sD[r], s = sS[r];
                    float2 pi = *(const float2*)(g_Pi + (size_t)d * 256 + col);
                    float2 pj = *(const float2*)(g_Pj + (size_t)s * 256 + col);
                    sA[r * 260 + col]     = to_tf32(fmaxf(acc[mf][nf][h*2+0] + pi.x + pj.x + bb.x, 0.f));
                    sA[r * 260 + col + 1] = to_tf32(fmaxf(acc[mf][nf][h*2+1] + pi.y + pj.y + bb.y, 0.f));
                }
            }
    }
    __syncthreads();

    // ---- stage 1: sA = relu(sA@A1 + b1) ----
    {
        float acc[2][16][4];
        gemm_stage<16>(sA, g_BtA1, 256, sW, sWu, tid, acc);
#pragma unroll
        for (int mf = 0; mf < 2; mf++)
#pragma unroll
            for (int nf = 0; nf < 16; nf++) {
                int col = wn * 128 + nf * 8 + lc * 2;
                float2 bb = *(const float2*)(A1_b + col);
#pragma unroll
                for (int h = 0; h < 2; h++) {
                    int r = wm * 32 + mf * 16 + h * 8 + lq;
                    sA[r * 260 + col]     = to_tf32(fmaxf(acc[mf][nf][h*2+0] + bb.x, 0.f));
                    sA[r * 260 + col + 1] = to_tf32(fmaxf(acc[mf][nf][h*2+1] + bb.y, 0.f));
                }
            }
    }
    __syncthreads();

    // ---- stage 2: sA = relu(sA@A2 + b2), fused attention scores ----
    {
        float acc[2][16][4];
        gemm_stage<16>(sA, g_BtA2, 256, sW, sWu, tid, acc);
        float sp[2][2][2] = {{{0.f,0.f},{0.f,0.f}},{{0.f,0.f},{0.f,0.f}}};
#pragma unroll
        for (int mf = 0; mf < 2; mf++)
#pragma unroll
            for (int nf = 0; nf < 16; nf++) {
                int col = wn * 128 + nf * 8 + lc * 2;
                float2 bb = *(const float2*)(A2_b + col);
                float2 av = *(const float2*)(attn + col);
#pragma unroll
                for (int h = 0; h < 2; h++) {
                    int r = wm * 32 + mf * 16 + h * 8 + lq;
                    float v0 = fmaxf(acc[mf][nf][h*2+0] + bb.x, 0.f);
                    float v1 = fmaxf(acc[mf][nf][h*2+1] + bb.y, 0.f);
                    sA[r * 260 + col]     = to_tf32(v0);
                    sA[r * 260 + col + 1] = to_tf32(v1);
                    sp[mf][h][nf >> 3] += v0 * av.x + v1 * av.y;
                }
            }
#pragma unroll
        for (int mf = 0; mf < 2; mf++)
#pragma unroll
            for (int h = 0; h < 2; h++)
#pragma unroll
                for (int g = 0; g < 2; g++) {
                    float v = sp[mf][h][g];
                    v += __shfl_xor_sync(0xffffffffu, v, 1);
                    v += __shfl_xor_sync(0xffffffffu, v, 2);
                    if (lc == 0)
                        sSc[(wm * 32 + mf * 16 + h * 8 + lq) * 4 + wn * 2 + g] = v;
                }
    }
    __syncthreads();

    // ---- stage 3: sA(cols 0..63) = relu(sA@Em0 + b) ----
    {
        float acc[2][4][4];
        gemm_stage<4>(sA, g_BtEm0, 256, sW, sWu, tid, acc);
#pragma unroll
        for (int mf = 0; mf < 2; mf++)
#pragma unroll
            for (int nf = 0; nf < 4; nf++) {
                int col = wn * 32 + nf * 8 + lc * 2;
                float2 bb = *(const float2*)(Em0_b + col);
#pragma unroll
                for (int h = 0; h < 2; h++) {
                    int r = wm * 32 + mf * 16 + h * 8 + lq;
                    sA[r * 260 + col]     = to_tf32(fmaxf(acc[mf][nf][h*2+0] + bb.x, 0.f));
                    sA[r * 260 + col + 1] = to_tf32(fmaxf(acc[mf][nf][h*2+1] + bb.y, 0.f));
                }
            }
    }
    __syncthreads();

    // ---- stage 4: sA(cols 0..63) = relu(sA@Em1 + b) ----
    {
        float acc[2][4][4];
        gemm_stage<4>(sA, g_BtEm1, 64, sW, sWu, tid, acc);
#pragma unroll
        for (int mf = 0; mf < 2; mf++)
#pragma unroll
            for (int nf = 0; nf < 4; nf++) {
                int col = wn * 32 + nf * 8 + lc * 2;
                float2 bb = *(const float2*)(Em1_b + col);
#pragma unroll
                for (int h = 0; h < 2; h++) {
                    int r = wm * 32 + mf * 16 + h * 8 + lq;
                    sA[r * 260 + col]     = to_tf32(fmaxf(acc[mf][nf][h*2+0] + bb.x, 0.f));
                    sA[r * 260 + col + 1] = to_tf32(fmaxf(acc[mf][nf][h*2+1] + bb.y, 0.f));
                }
            }
    }
    __syncthreads();

    // ---- stage 5: out_edge = relu(sA@Em2 + b) + Et ----
    {
        float acc[2][4][4];
        gemm_stage<4>(sA, g_BtEm2, 64, sW, sWu, tid, acc);
#pragma unroll
        for (int mf = 0; mf < 2; mf++)
#pragma unroll
            for (int nf = 0; nf < 4; nf++) {
                int col = wn * 32 + nf * 8 + lc * 2;
                float2 bb = *(const float2*)(Em2_b + col);
#pragma unroll
                for (int h = 0; h < 2; h++) {
                    int r = wm * 32 + mf * 16 + h * 8 + lq;
                    if (e0 + r < E) {
                        float2 o;
                        o.x = fmaxf(acc[mf][nf][h*2+0] + bb.x, 0.f) + sEt[r * 66 + col];
                        o.y = fmaxf(acc[mf][nf][h*2+1] + bb.y, 0.f) + sEt[r * 66 + col + 1];
                        *(float2*)(out_edge + (size_t)(e0 + r) * 64 + col) = o;
                    }
                }
            }
    }
    __syncthreads();

    // ---- write scores + segment max ----
    for (int i = tid; i < 512; i += 256) {
        int r = i >> 2, h = i & 3;
        if (e0 + r < E) {
            float v = sSc[i];
            g_scores[(size_t)(e0 + r) * 4 + h] = v;
            atomicMaxFloat(&g_smax[(size_t)sD[r] * 4 + h], v);
        }
    }
}

// ---------------- tf32 warp-MMA GEMM (node-level) ----------------
template<int BN, bool BIASRELU>
__global__ void __launch_bounds__(256)
mma_gemm(const float* __restrict__ A, const float* __restrict__ Bt,
         const float* __restrict__ bias, float* __restrict__ C,
         int M, int K, int ldc)
{
    constexpr int NF = BN / 16;
    constexpr int WN = BN / 2;
    __shared__ float As[128][20];
    __shared__ float Bs[BN][20];

    const int tid = threadIdx.x;
    const int lane = tid & 31, wid = tid >> 5;
    const int wm = wid & 3, wn = wid >> 2;
    const int m0 = blockIdx.x * 128;
    const int n0 = blockIdx.y * BN;
    const int lq = lane >> 2;
    const int lc = lane & 3;

    float acc[2][NF][4];
#pragma unroll
    for (int i = 0; i < 2; i++)
#pragma unroll
        for (int j = 0; j < NF; j++)
#pragma unroll
            for (int q = 0; q < 4; q++) acc[i][j][q] = 0.0f;

    for (int k0 = 0; k0 < K; k0 += 16) {
#pragma unroll
        for (int i = tid; i < 512; i += 256) {
            int m = i >> 2, q = i & 3;
            float4 v = make_float4(0.f, 0.f, 0.f, 0.f);
            int row = m0 + m;
            if (row < M) v = *reinterpret_cast<const float4*>(A + (size_t)row * K + k0 + q * 4);
            v.x = to_tf32(v.x); v.y = to_tf32(v.y); v.z = to_tf32(v.z); v.w = to_tf32(v.w);
            *reinterpret_cast<float4*>(&As[m][q * 4]) = v;
        }
#pragma unroll
        for (int i = tid; i < BN * 4; i += 256) {
            int n = i >> 2, q = i & 3;
            float4 v = *reinterpret_cast<const float4*>(Bt + (size_t)(n0 + n) * K + k0 + q * 4);
            *reinterpret_cast<float4*>(&Bs[n][q * 4]) = v;
        }
        __syncthreads();

#pragma unroll
        for (int kk = 0; kk < 16; kk += 8) {
            unsigned a[2][4];
#pragma unroll
            for (int mf = 0; mf < 2; mf++) {
                int m = wm * 32 + mf * 16 + lq;
                a[mf][0] = __float_as_uint(As[m][kk + lc]);
                a[mf][1] = __float_as_uint(As[m + 8][kk + lc]);
                a[mf][2] = __float_as_uint(As[m][kk + 4 + lc]);
                a[mf][3] = __float_as_uint(As[m + 8][kk + 4 + lc]);
            }
            unsigned b[NF][2];
#pragma unroll
            for (int nf = 0; nf < NF; nf++) {
                int n = wn * WN + nf * 8 + lq;
                b[nf][0] = __float_as_uint(Bs[n][kk + lc]);
                b[nf][1] = __float_as_uint(Bs[n][kk + 4 + lc]);
            }
#pragma unroll
            for (int mf = 0; mf < 2; mf++)
#pragma unroll
                for (int nf = 0; nf < NF; nf++)
                    mma_tf32(acc[mf][nf], a[mf], b[nf]);
        }
        __syncthreads();
    }

#pragma unroll
    for (int mf = 0; mf < 2; mf++) {
#pragma unroll
        for (int nf = 0; nf < NF; nf++) {
            int row = m0 + wm * 32 + mf * 16 + lq;
            int col = n0 + wn * WN + nf * 8 + lc * 2;
            float2 bv = make_float2(0.f, 0.f);
            if (BIASRELU) bv = *reinterpret_cast<const float2*>(bias + col);
            float2 v0 = make_float2(acc[mf][nf][0], acc[mf][nf][1]);
            float2 v1 = make_float2(acc[mf][nf][2], acc[mf][nf][3]);
            if (BIASRELU) {
                v0.x = fmaxf(v0.x + bv.x, 0.f); v0.y = fmaxf(v0.y + bv.y, 0.f);
                v1.x = fmaxf(v1.x + bv.x, 0.f); v1.y = fmaxf(v1.y + bv.y, 0.f);
            }
            if (row < M)
                *reinterpret_cast<float2*>(C + (size_t)row * ldc + col) = v0;
            if (row + 8 < M)
                *reinterpret_cast<float2*>(C + (size_t)(row + 8) * ldc + col) = v1;
        }
    }
}

// transpose W[K,N] -> Bt[N,K], rounded to tf32
__global__ void transpose_tf32(const float* __restrict__ W, float* __restrict__ Bt, int K, int Nd)
{
    int i = blockIdx.x * blockDim.x + threadIdx.x;
    if (i >= K * Nd) return;
    int n = i / K, k = i % K;
    Bt[i] = to_tf32(W[(size_t)k * Nd + n]);
}

// ---------------- generic tiled fp32 SGEMM ----------------
template<int BM, int BN, int BK, int TM, int TN, bool RELU, bool BIAS, bool RES>
__global__ void __launch_bounds__((BM / TM) * (BN / TN))
sgemm(const float* __restrict__ A, int lda,
      const float* __restrict__ W,
      const float* __restrict__ bias,
      const float* __restrict__ res, int ldres,
      float* __restrict__ C, int ldc,
      int M, int N, int K)
{
    constexpr int NT = (BM / TM) * (BN / TN);
    __shared__ float As[BK][BM + 4];
    __shared__ float Ws[BK][BN];

    const int tid = threadIdx.x;
    const int tx = tid % (BN / TN);
    const int ty = tid / (BN / TN);
    const int m0 = blockIdx.x * BM;
    const int n0 = blockIdx.y * BN;

    float acc[TM][TN];
#pragma unroll
    for (int i = 0; i < TM; i++)
#pragma unroll
        for (int j = 0; j < TN; j++) acc[i][j] = 0.0f;

    for (int k0 = 0; k0 < K; k0 += BK) {
#pragma unroll
        for (int i = tid; i < BM * BK / 4; i += NT) {
            int m  = i / (BK / 4);
            int k4 = i % (BK / 4);
            float4 v = make_float4(0.f, 0.f, 0.f, 0.f);
            int row = m0 + m;
            if (row < M)
                v = *reinterpret_cast<const float4*>(A + (size_t)row * lda + k0 + k4 * 4);
            As[k4 * 4 + 0][m] = v.x;
            As[k4 * 4 + 1][m] = v.y;
            As[k4 * 4 + 2][m] = v.z;
            As[k4 * 4 + 3][m] = v.w;
        }
#pragma unroll
        for (int i = tid; i < BK * BN / 4; i += NT) {
            int k  = i / (BN / 4);
            int n4 = i % (BN / 4);
            *reinterpret_cast<float4*>(&Ws[k][n4 * 4]) =
                *reinterpret_cast<const float4*>(W + (size_t)(k0 + k) * N + n0 + n4 * 4);
        }
        __syncthreads();

#pragma unroll
        for (int k = 0; k < BK; k++) {
            float a[TM], b[TN];
#pragma unroll
            for (int i = 0; i < TM; i++) a[i] = As[k][ty * TM + i];
#pragma unroll
            for (int j = 0; j < TN; j++) b[j] = Ws[k][tx * TN + j];
#pragma unroll
            for (int i = 0; i < TM; i++)
#pragma unroll
                for (int j = 0; j < TN; j++)
                    acc[i][j] = fmaf(a[i], b[j], acc[i][j]);
        }
        __syncthreads();
    }

#pragma unroll
    for (int i = 0; i < TM; i++) {
        int row = m0 + ty * TM + i;
        if (row >= M) continue;
#pragma unroll
        for (int j = 0; j < TN; j++) {
            int col = n0 + tx * TN + j;
            float v = acc[i][j];
            if (BIAS) v += bias[col];
            if (RELU) v = fmaxf(v, 0.0f);
            if (RES)  v += res[(size_t)row * ldres + col];
            C[(size_t)row * ldc + col] = v;
        }
    }
}

// ---------------- small helper kernels ----------------
__global__ void init_kernel(int N)
{
    int i = blockIdx.x * blockDim.x + threadIdx.x;
    if (i < N * 4) { g_smax[i] = -INFINITY; g_den[i] = 0.0f; }
    if (i < N * 256) g_agg[i] = 0.0f;
    if (i < N) g_deg[i] = 1.0f;
}

__global__ void ex_kernel(const int* __restrict__ dst, int E)
{
    int i = blockIdx.x * blockDim.x + threadIdx.x;
    if (i >= E * 4) return;
    int e = i >> 2, h = i & 3;
    int d = dst[e];
    float v = expf(g_scores[i] - g_smax[d * 4 + h]);
    g_ex[i] = v;
    atomicAdd(&g_den[d * 4 + h], v);
}

__global__ void agg_kernel(const int* __restrict__ src, const int* __restrict__ dst, int E,
                           const float* __restrict__ linW, float* __restrict__ attn_out)
{
    int idx = blockIdx.x * blockDim.x + threadIdx.x;
    int e = idx >> 6;
    int t = idx & 63;
    if (e >= E) return;
    int d = dst[e], s = src[e];
    int h = t >> 4;
    float alpha = g_ex[e * 4 + h] / g_den[(size_t)d * 4 + h];
    if (t == 0) {
        float aw = 0.0f;
#pragma unroll
        for (int hh = 0; hh < 4; hh++)
            aw += (g_ex[e * 4 + hh] / g_den[(size_t)d * 4 + hh]) * linW[hh];
        attn_out[e] = aw;
    }
    float4 xj = reinterpret_cast<const float4*>(g_Xni + (size_t)s * 256)[t];
    float4 m = make_float4(xj.x * alpha, xj.y * alpha, xj.z * alpha, xj.w * alpha);
    atomicAdd4(reinterpret_cast<float4*>(g_agg + (size_t)d * 256 + t * 4), m);
}

__global__ void deg_kernel(const int* __restrict__ src, const int* __restrict__ dst, int E)
{
    int e = blockIdx.x * blockDim.x + threadIdx.x;
    if (e >= E) return;
    int s = src[e];
    if (s != dst[e]) atomicAdd(&g_deg[s], 1.0f);
}

__global__ void dinv_kernel(int N)
{
    int n = blockIdx.x * blockDim.x + threadIdx.x;
    if (n < N) g_dinv[n] = rsqrtf(g_deg[n]);
}

__global__ void outinit_kernel(const float* __restrict__ gcn_b, float* __restrict__ out, int N)
{
    int i = blockIdx.x * blockDim.x + threadIdx.x;
    if (i >= N * 64) return;
    int n = i >> 6;
    float di = g_dinv[n];
    out[i] = gcn_b[i & 63] + di * di * g_xg[i];
}

__global__ void gcn_scatter_kernel(const int* __restrict__ src, const int* __restrict__ dst,
                                   int E, float* __restrict__ out)
{
    int idx = blockIdx.x * blockDim.x + threadIdx.x;
    int e = idx >> 4;
    int t = idx & 15;
    if (e >= E) return;
    int s = src[e], d = dst[e];
    if (s == d) return;
    float w = g_dinv[s] * g_dinv[d];
    float4 v = reinterpret_cast<const float4*>(g_xg + (size_t)s * 64)[t];
    float4 m = make_float4(v.x * w, v.y * w, v.z * w, v.w * w);
    atomicAdd4(reinterpret_cast<float4*>(out + (size_t)d * 64 + t * 4), m);
}

// ---------------- launch ----------------
extern "C" void kernel_launch(void* const* d_in, const int* in_sizes, int n_in,
                              void* d_out, int out_size)
{
    const float* node = (const float*)d_in[0];
    const float* edge = (const float*)d_in[1];
    const int*   ei   = (const int*)d_in[2];
    const float* W_ni = (const float*)d_in[3];
    const float* W_nj = (const float*)d_in[4];
    const float* W_eij= (const float*)d_in[5];
    const float* W_nt = (const float*)d_in[6];
    const float* b_nt = (const float*)d_in[7];
    const float* W_et = (const float*)d_in[8];
    const float* b_et = (const float*)d_in[9];
    const float* A0_W = (const float*)d_in[10];
    const float* A0_b = (const float*)d_in[11];
    const float* A1_W = (const float*)d_in[12];
    const float* A1_b = (const float*)d_in[13];
    const float* A2_W = (const float*)d_in[14];
    const float* A2_b = (const float*)d_in[15];
    const float* attn = (const float*)d_in[16];
    const float* Nm0_W= (const float*)d_in[17];
    const float* Nm0_b= (const float*)d_in[18];
    const float* Nm1_W= (const float*)d_in[19];
    const float* Nm1_b= (const float*)d_in[20];
    const float* Nm2_W= (const float*)d_in[21];
    const float* Nm2_b= (const float*)d_in[22];
    const float* Em0_W= (const float*)d_in[23];
    const float* Em0_b= (const float*)d_in[24];
    const float* Em1_W= (const float*)d_in[25];
    const float* Em1_b= (const float*)d_in[26];
    const float* Em2_W= (const float*)d_in[27];
    const float* Em2_b= (const float*)d_in[28];
    const float* linW = (const float*)d_in[29];
    const float* gcnW = (const float*)d_in[30];
    const float* gcnb = (const float*)d_in[31];

    const int N = in_sizes[0] / 256;
    const int E = in_sizes[2] / 2;
    const int* src = ei;
    const int* dst = ei + E;

    float* out      = (float*)d_out;
    float* out_node = out;
    float* out_edge = out + (size_t)N * 64;
    float* out_attn = out_edge + (size_t)E * 64;

    void* p;
    cudaGetSymbolAddress(&p, g_Xni);   float* pXni = (float*)p;
    cudaGetSymbolAddress(&p, g_Xnt);   float* pXnt = (float*)p;
    cudaGetSymbolAddress(&p, g_Pi);    float* pPi  = (float*)p;
    cudaGetSymbolAddress(&p, g_Pj);    float* pPj  = (float*)p;
    cudaGetSymbolAddress(&p, g_Wcomb); float* pWcomb = (float*)p;
    cudaGetSymbolAddress(&p, g_Wfold); float* pWfold = (float*)p;
    cudaGetSymbolAddress(&p, g_agg);   float* pAgg = (float*)p;
    cudaGetSymbolAddress(&p, g_NM0);   float* pNM0 = (float*)p;
    cudaGetSymbolAddress(&p, g_NM1);   float* pNM1 = (float*)p;
    cudaGetSymbolAddress(&p, g_nodeout); float* pNodeOut = (float*)p;
    cudaGetSymbolAddress(&p, g_xg);    float* pXg  = (float*)p;
    cudaGetSymbolAddress(&p, g_BtA1);   float* pBtA1 = (float*)p;
    cudaGetSymbolAddress(&p, g_BtA2);   float* pBtA2 = (float*)p;
    cudaGetSymbolAddress(&p, g_BtComb); float* pBtComb = (float*)p;
    cudaGetSymbolAddress(&p, g_BtEm0);  float* pBtEm0 = (float*)p;
    cudaGetSymbolAddress(&p, g_BtEm1);  float* pBtEm1 = (float*)p;
    cudaGetSymbolAddress(&p, g_BtEm2);  float* pBtEm2 = (float*)p;
    cudaGetSymbolAddress(&p, g_BtEt);   float* pBtEt = (float*)p;
    cudaGetSymbolAddress(&p, g_BtNi);   float* pBtNi = (float*)p;
    cudaGetSymbolAddress(&p, g_BtFold); float* pBtFold = (float*)p;
    cudaGetSymbolAddress(&p, g_BtPj);   float* pBtPj = (float*)p;

    const int TPB = 256;
    const int MT_N = (N + 127) / 128;
    const int ET = (E + 127) / 128;               // fused edge tiles (128 rows)
    const int FUSED_SMEM = 52736 * 4;             // 206 KB
    cudaFuncSetAttribute(edge_fused, cudaFuncAttributeMaxDynamicSharedMemorySize, FUSED_SMEM);

    // 1. init reductions
    init_kernel<<<(N * 256 + TPB - 1) / TPB, TPB>>>(N);

    // 2a. weight folds (fp32)
    {
        dim3 g(2, 2);
        sgemm<128,128,16,8,8,false,false,false><<<g, 256>>>(W_nj, 256, A0_W, nullptr, nullptr, 0, pWfold, 256, 256, 256, 256);
    }
    {
        dim3 g(1, 2);
        sgemm<128,128,16,8,8,false,false,false><<<g, 256>>>(W_eij, 256, A0_W + 256 * 256, nullptr, nullptr, 0, pWcomb, 256, 128, 256, 256);
    }

    // 2b. transposed tf32 weights
    transpose_tf32<<<256, 256>>>(A1_W, pBtA1, 256, 256);
    transpose_tf32<<<256, 256>>>(A2_W, pBtA2, 256, 256);
    transpose_tf32<<<128, 256>>>(pWcomb, pBtComb, 128, 256);
    transpose_tf32<<<64, 256>>>(Em0_W, pBtEm0, 256, 64);
    transpose_tf32<<<16, 256>>>(Em1_W, pBtEm1, 64, 64);
    transpose_tf32<<<16, 256>>>(Em2_W, pBtEm2, 64, 64);
    transpose_tf32<<<32, 256>>>(W_et, pBtEt, 128, 64);
    transpose_tf32<<<256, 256>>>(W_ni, pBtNi, 256, 256);
    transpose_tf32<<<256, 256>>>(pWfold, pBtFold, 256, 256);
    transpose_tf32<<<256, 256>>>(A0_W + 512 * 256, pBtPj, 256, 256);

    // 2c. node-level projections
    {
        dim3 g(MT_N, 2);
        mma_gemm<128, false><<<g, 256>>>(node, pBtNi,   nullptr, pXni, N, 256, 256);
        mma_gemm<128, false><<<g, 256>>>(node, pBtFold, nullptr, pPi,  N, 256, 256);
        mma_gemm<128, false><<<g, 256>>>(pXni, pBtPj,   nullptr, pPj,  N, 256, 256);
    }
    {
        dim3 g(MT_N, 1);
        sgemm<128,64,16,8,4,false,true,false><<<g, 256>>>(node, 256, W_nt, b_nt, nullptr, 0, pXnt, 64, N, 64, 256);
    }

    // 3. fused edge chain (Et + comb+gather+relu -> A1 -> A2+scores -> Em0..Em2 -> out_edge)
    edge_fused<<<ET, 256, FUSED_SMEM>>>(edge, src, dst, E, A0_b, A1_b, A2_b,
                                        Em0_b, Em1_b, Em2_b, b_et, attn, out_edge);

    // 4. softmax denominators + message aggregation
    ex_kernel<<<((size_t)E * 4 + TPB - 1) / TPB, TPB>>>(dst, E);
    agg_kernel<<<((size_t)E * 64 + TPB - 1) / TPB, TPB>>>(src, dst, E, linW, out_attn);

    // 5. node MLP (+ residual node@W_nt + b_nt)
    {
        dim3 g(MT_N, 1);
        sgemm<128,64,16,8,4,true,true,false><<<g, 256>>>(pAgg, 256, Nm0_W, Nm0_b, nullptr, 0, pNM0, 64, N, 64, 256);
        sgemm<128,64,16,8,4,true,true,false><<<g, 256>>>(pNM0, 64, Nm1_W, Nm1_b, nullptr, 0, pNM1, 64, N, 64, 64);
        sgemm<128,64,16,8,4,true,true,true><<<g, 256>>>(pNM1, 64, Nm2_W, Nm2_b, pXnt, 64, pNodeOut, 64, N, 64, 64);
    }

    // 6. GCN
    deg_kernel<<<(E + TPB - 1) / TPB, TPB>>>(src, dst, E);
    dinv_kernel<<<(N + TPB - 1) / TPB, TPB>>>(N);
    {
        dim3 g(MT_N, 1);
        sgemm<128,64,16,8,4,false,false,false><<<g, 256>>>(pNodeOut, 64, gcnW, nullptr, nullptr, 0, pXg, 64, N, 64, 64);
    }
    outinit_kernel<<<(N * 64 + TPB - 1) / TPB, TPB>>>(gcnb, out_node, N);
    gcn_scatter_kernel<<<((size_t)E * 16 + TPB - 1) / TPB, TPB>>>(src, dst, E, out_node);
}